// round 1
// baseline (speedup 1.0000x reference)
#include <cuda_runtime.h>
#include <math.h>

#define PP 4
#define BB 128
#define DD 512
#define NN 32768
#define KK 10
#define NT 128
#define NTILES (NN/NT)   /* 256 */
#define SCALE_C 10.0f
#define INV_TEMP 2.0f
#define SIM_THR 0.7f
#define KLW 0.4916666666666667f
#define NEG_INF_F (-1e30f)

// ---------------- device scratch (no allocations allowed) ----------------
__device__ float g_img[PP*BB*DD];
__device__ float g_txt[PP*BB*DD];
__device__ float g_fn2[PP*BB];
__device__ float g_cn2[PP*NN];
__device__ float g_imgsim[PP*BB*BB];
__device__ float g_txtsim[PP*BB*BB];
__device__ unsigned char g_negmask[NN];
__device__ float g_partial[PP*NTILES*BB];
__device__ float g_negsum[PP*BB];
__device__ float g_possum[PP*BB];
__device__ float g_alignpart[PP];

// ---------------- helpers ----------------
__device__ __forceinline__ float blockReduceSum(float v) {
    __shared__ float sh[32];
    int lane = threadIdx.x & 31, w = threadIdx.x >> 5;
    #pragma unroll
    for (int o = 16; o; o >>= 1) v += __shfl_down_sync(0xffffffffu, v, o);
    if (!lane) sh[w] = v;
    __syncthreads();
    int nw = (blockDim.x + 31) >> 5;
    v = (threadIdx.x < nw) ? sh[threadIdx.x] : 0.f;
    if (!w) {
        #pragma unroll
        for (int o = 16; o; o >>= 1) v += __shfl_down_sync(0xffffffffu, v, o);
    }
    __syncthreads();
    return v;  // valid on thread 0
}

// ---------------- 1. normalize feature/text rows, compute fn2 ----------------
// grid: P*B blocks of 128 threads. pb = p*B+b
__global__ void prep_kernel(const float* __restrict__ feat,
                            const float* __restrict__ text) {
    int pb = blockIdx.x;
    int p = pb / BB, b = pb % BB;
    const float* f = feat + (size_t)pb * DD;
    const float* t = text + ((size_t)b * PP + p) * DD;
    float s1 = 0.f, s2 = 0.f;
    for (int d = threadIdx.x; d < DD; d += 128) {
        float v = f[d]; s1 += v * v;
        float w = t[d]; s2 += w * w;
    }
    __shared__ float inv1, inv2;
    float r1 = blockReduceSum(s1);
    if (threadIdx.x == 0) {
        g_fn2[pb] = r1;
        inv1 = 1.f / fmaxf(sqrtf(r1), 1e-12f);
    }
    float r2 = blockReduceSum(s2);
    if (threadIdx.x == 0) inv2 = 1.f / fmaxf(sqrtf(r2), 1e-12f);
    __syncthreads();
    for (int d = threadIdx.x; d < DD; d += 128) {
        g_img[(size_t)pb * DD + d] = f[d] * inv1;
        g_txt[(size_t)pb * DD + d] = t[d] * inv2;
    }
}

// ---------------- 2. center squared norms ----------------
// grid: (P*N)/8 blocks of 256 threads, one warp per row
__global__ void cn2_kernel(const float* __restrict__ centers) {
    int warp = threadIdx.x >> 5, lane = threadIdx.x & 31;
    size_t row = (size_t)blockIdx.x * 8 + warp;
    const float4* c = (const float4*)(centers + row * DD);
    float s = 0.f;
    #pragma unroll
    for (int q = lane; q < DD / 4; q += 32) {
        float4 v = c[q];
        s += v.x * v.x + v.y * v.y + v.z * v.z + v.w * v.w;
    }
    #pragma unroll
    for (int o = 16; o; o >>= 1) s += __shfl_down_sync(0xffffffffu, s, o);
    if (!lane) g_cn2[row] = s;
}

// ---------------- 3. neg mask ----------------
__global__ void mask_init_kernel() {
    int i = blockIdx.x * 256 + threadIdx.x;
    if (i < NN) g_negmask[i] = 1;
}
__global__ void mask_scatter_kernel(const int* __restrict__ ci,
                                    const int* __restrict__ pos) {
    int i = blockIdx.x * 256 + threadIdx.x;
    if (i < BB * KK)            g_negmask[ci[i]] = 0;
    else if (i < BB * KK + BB)  g_negmask[pos[i - BB * KK]] = 0;
}

// ---------------- 4. big GEMM + exp-dist partial sums ----------------
// grid (NTILES, P), 256 threads, 128(B) x 128(N) tile, 8x8 per thread
__global__ __launch_bounds__(256) void neg_gemm_kernel(
        const float* __restrict__ feat, const float* __restrict__ centers) {
    int p = blockIdx.y;
    int nt = blockIdx.x;
    int n0 = nt * NT;
    __shared__ float As[32][132];
    __shared__ float Bs[32][132];
    int tid = threadIdx.x;
    int tx = tid & 15, ty = tid >> 4;
    float acc[8][8];
    #pragma unroll
    for (int i = 0; i < 8; i++)
        #pragma unroll
        for (int j = 0; j < 8; j++) acc[i][j] = 0.f;

    const float* fbase = feat + (size_t)p * BB * DD;
    const float* cbase = centers + (size_t)p * NN * DD + (size_t)n0 * DD;

    for (int d0 = 0; d0 < DD; d0 += 32) {
        #pragma unroll
        for (int k = 0; k < 4; k++) {
            int idx = tid + k * 256;     // 0..1023 float4 slots
            int row = idx >> 3;
            int dq = idx & 7;
            float4 v = *(const float4*)(fbase + (size_t)row * DD + d0 + dq * 4);
            As[dq * 4 + 0][row] = v.x; As[dq * 4 + 1][row] = v.y;
            As[dq * 4 + 2][row] = v.z; As[dq * 4 + 3][row] = v.w;
            float4 w = *(const float4*)(cbase + (size_t)row * DD + d0 + dq * 4);
            Bs[dq * 4 + 0][row] = w.x; Bs[dq * 4 + 1][row] = w.y;
            Bs[dq * 4 + 2][row] = w.z; Bs[dq * 4 + 3][row] = w.w;
        }
        __syncthreads();
        #pragma unroll
        for (int kk = 0; kk < 32; kk++) {
            float a[8], bb[8];
            #pragma unroll
            for (int i = 0; i < 8; i++) a[i] = As[kk][ty + 16 * i];
            #pragma unroll
            for (int j = 0; j < 8; j++) bb[j] = Bs[kk][tx + 16 * j];
            #pragma unroll
            for (int i = 0; i < 8; i++)
                #pragma unroll
                for (int j = 0; j < 8; j++) acc[i][j] += a[i] * bb[j];
        }
        __syncthreads();
    }

    float fn2v[8];
    #pragma unroll
    for (int i = 0; i < 8; i++) fn2v[i] = g_fn2[p * BB + ty + 16 * i];
    float rowsum[8];
    #pragma unroll
    for (int i = 0; i < 8; i++) rowsum[i] = 0.f;

    #pragma unroll
    for (int j = 0; j < 8; j++) {
        int n = n0 + tx + 16 * j;
        float cn2v = g_cn2[(size_t)p * NN + n];
        if (g_negmask[n]) {
            #pragma unroll
            for (int i = 0; i < 8; i++) {
                float pd2 = fn2v[i] + cn2v - 2.f * acc[i][j];
                rowsum[i] += expf(-SCALE_C * sqrtf(fmaxf(pd2, 1e-12f)));
            }
        }
    }
    #pragma unroll
    for (int i = 0; i < 8; i++) {
        #pragma unroll
        for (int o = 8; o; o >>= 1)
            rowsum[i] += __shfl_down_sync(0xffffffffu, rowsum[i], o, 16);
    }
    if (tx == 0) {
        #pragma unroll
        for (int i = 0; i < 8; i++)
            g_partial[((size_t)p * NTILES + nt) * BB + ty + 16 * i] = rowsum[i];
    }
}

// ---------------- 5. reduce partials -> negsum ----------------
// grid P*B blocks of 256 threads
__global__ void neg_reduce_kernel() {
    int pb = blockIdx.x;
    int p = pb / BB, b = pb % BB;
    float s = g_partial[((size_t)p * NTILES + threadIdx.x) * BB + b];
    float r = blockReduceSum(s);
    if (threadIdx.x == 0) g_negsum[pb] = r;
}

// ---------------- 6. positive distances ----------------
// grid P*B blocks of 32 threads (1 warp)
__global__ void pos_kernel(const float* __restrict__ feat,
                           const float* __restrict__ centers,
                           const int* __restrict__ ci) {
    int pb = blockIdx.x;
    int p = pb / BB, b = pb % BB;
    int lane = threadIdx.x;
    const float4* f = (const float4*)(feat + (size_t)pb * DD);
    float fn2v = g_fn2[pb];
    float possum = 0.f;
    for (int k = 0; k < KK; k++) {
        int idx = ci[b * KK + k];
        const float4* c = (const float4*)(centers + ((size_t)p * NN + idx) * DD);
        float dot = 0.f;
        #pragma unroll
        for (int q = lane; q < DD / 4; q += 32) {
            float4 a = f[q], bv = c[q];
            dot += a.x * bv.x + a.y * bv.y + a.z * bv.z + a.w * bv.w;
        }
        #pragma unroll
        for (int o = 16; o; o >>= 1) dot += __shfl_down_sync(0xffffffffu, dot, o);
        if (lane == 0) {
            float pn2 = g_cn2[(size_t)p * NN + idx];
            float pd2 = fn2v + pn2 - 2.f * dot;
            possum += expf(-SCALE_C * sqrtf(fmaxf(pd2, 1e-12f)));
        }
    }
    if (lane == 0) g_possum[pb] = possum;
}

// ---------------- 7. similarity matrices (img and txt) ----------------
// grid (2, P): x=0 -> img, x=1 -> txt. 256 threads, 128x128 output, 8x8/thread
__global__ __launch_bounds__(256) void sim_gemm_kernel() {
    int p = blockIdx.y;
    const float* src = blockIdx.x ? g_txt : g_img;
    float* dst = blockIdx.x ? g_txtsim : g_imgsim;
    src += (size_t)p * BB * DD;
    dst += (size_t)p * BB * BB;
    __shared__ float As[32][132];
    int tid = threadIdx.x;
    int tx = tid & 15, ty = tid >> 4;
    float acc[8][8];
    #pragma unroll
    for (int i = 0; i < 8; i++)
        #pragma unroll
        for (int j = 0; j < 8; j++) acc[i][j] = 0.f;

    for (int d0 = 0; d0 < DD; d0 += 32) {
        #pragma unroll
        for (int k = 0; k < 4; k++) {
            int idx = tid + k * 256;
            int row = idx >> 3;
            int dq = idx & 7;
            float4 v = *(const float4*)(src + (size_t)row * DD + d0 + dq * 4);
            As[dq * 4 + 0][row] = v.x; As[dq * 4 + 1][row] = v.y;
            As[dq * 4 + 2][row] = v.z; As[dq * 4 + 3][row] = v.w;
        }
        __syncthreads();
        #pragma unroll
        for (int kk = 0; kk < 32; kk++) {
            float a[8], bb[8];
            #pragma unroll
            for (int i = 0; i < 8; i++) a[i] = As[kk][ty + 16 * i];
            #pragma unroll
            for (int j = 0; j < 8; j++) bb[j] = As[kk][tx + 16 * j];
            #pragma unroll
            for (int i = 0; i < 8; i++)
                #pragma unroll
                for (int j = 0; j < 8; j++) acc[i][j] += a[i] * bb[j];
        }
        __syncthreads();
    }
    #pragma unroll
    for (int i = 0; i < 8; i++) {
        int b = ty + 16 * i;
        #pragma unroll
        for (int j = 0; j < 8; j++) {
            int c = tx + 16 * j;
            dst[b * BB + c] = acc[i][j] * INV_TEMP;
        }
    }
}

// ---------------- 8. align / KL loss per partition ----------------
// grid P blocks of 128 threads; thread b owns row b
__global__ void align_kernel() {
    int p = blockIdx.x;
    int b = threadIdx.x;
    const float* imrow = g_imgsim + ((size_t)p * BB + b) * BB;
    const float* txrow = g_txtsim + ((size_t)p * BB + b) * BB;
    __shared__ unsigned char shv[BB];
    bool v = false;
    for (int c = 0; c < BB; c++)
        if (imrow[c] > SIM_THR && txrow[c] > SIM_THR) v = true;
    shv[b] = v ? 1 : 0;
    __syncthreads();

    float mi = NEG_INF_F, mt = NEG_INF_F;
    for (int c = 0; c < BB; c++)
        if (shv[c]) { mi = fmaxf(mi, imrow[c]); mt = fmaxf(mt, txrow[c]); }
    float si = 0.f, st = 0.f;
    for (int c = 0; c < BB; c++)
        if (shv[c]) { si += expf(imrow[c] - mi); st += expf(txrow[c] - mt); }
    float lsei = logf(si) + mi;
    float lset = logf(st) + mt;
    float kl1 = 0.f, kl2 = 0.f;
    for (int c = 0; c < BB; c++) {
        if (shv[c]) {
            float ilp = imrow[c] - lsei;
            float tlp = txrow[c] - lset;
            kl1 += expf(tlp) * (tlp - ilp);
            kl2 += expf(ilp) * (ilp - tlp);
        }
    }
    float c1 = v ? kl1 : 0.f;
    float c2 = v ? kl2 : 0.f;
    float nvf = v ? 1.f : 0.f;
    float r1 = blockReduceSum(c1);
    __shared__ float sr1;
    if (b == 0) sr1 = r1;
    float r2 = blockReduceSum(c2);
    __shared__ float sr2;
    if (b == 0) sr2 = r2;
    float nv = blockReduceSum(nvf);
    if (b == 0) {
        int n = (int)(nv + 0.5f);
        float per = (n > 0) ? 0.5f * (sr1 + sr2) / (float)max(n, 1) : 0.f;
        g_alignpart[p] = per;
    }
}

// ---------------- 9. final combine ----------------
__global__ void final_kernel(float* __restrict__ out) {
    int b = threadIdx.x;
    __shared__ float sacc;
    if (b == 0) sacc = 0.f;
    __syncthreads();
    for (int p = 0; p < PP; p++) {
        float v = logf(g_negsum[p * BB + b]) - logf(g_possum[p * BB + b]);
        float r = blockReduceSum(v);
        if (b == 0) {
            float lp = r / (float)BB;
            if (isnan(lp)) lp = 0.f;
            sacc += lp;
        }
        __syncthreads();
    }
    if (b == 0) {
        float contrastive = sacc / (float)PP;
        float align = g_alignpart[0] + g_alignpart[1] + g_alignpart[2] + g_alignpart[3];
        out[0] = contrastive + KLW * align;
        out[1] = contrastive;
        out[2] = align;
    }
}

// ---------------- 10. pos_vid gather ----------------
__global__ void posvid_kernel(const int* __restrict__ vid,
                              const int* __restrict__ ci,
                              float* __restrict__ out) {
    int i = blockIdx.x * 256 + threadIdx.x;
    if (i < BB * KK) out[3 + i] = (float)vid[ci[i]];
}

// ---------------- launch ----------------
extern "C" void kernel_launch(void* const* d_in, const int* in_sizes, int n_in,
                              void* d_out, int out_size) {
    const float* feature = (const float*)d_in[0];
    const float* text    = (const float*)d_in[1];
    const float* centers = (const float*)d_in[2];
    const int*   pos     = (const int*)d_in[3];
    const int*   ci      = (const int*)d_in[4];
    const int*   vid     = (const int*)d_in[5];
    float* out = (float*)d_out;

    prep_kernel<<<PP * BB, 128>>>(feature, text);
    cn2_kernel<<<(PP * NN) / 8, 256>>>(centers);
    mask_init_kernel<<<NN / 256, 256>>>();
    mask_scatter_kernel<<<(BB * KK + BB + 255) / 256, 256>>>(ci, pos);
    neg_gemm_kernel<<<dim3(NTILES, PP), 256>>>(feature, centers);
    neg_reduce_kernel<<<PP * BB, 256>>>();
    pos_kernel<<<PP * BB, 32>>>(feature, centers, ci);
    sim_gemm_kernel<<<dim3(2, PP), 256>>>();
    align_kernel<<<PP, 128>>>();
    final_kernel<<<1, 128>>>(out);
    posvid_kernel<<<(BB * KK + 255) / 256, 256>>>(vid, ci, out);
}

// round 5
// speedup vs baseline: 2.1490x; 2.1490x over previous
#include <cuda_runtime.h>
#include <math.h>
#include <stdint.h>

#define PP 4
#define BB 128
#define DD 512
#define NN 32768
#define KK 10
#define NT 128
#define NTILES (NN/NT)   /* 256 */
#define SCALE_C 10.0f
#define INV_TEMP 2.0f
#define SIM_THR 0.7f
#define KLW 0.4916666666666667f
#define NEG_INF_F (-1e30f)
#define SA 136           /* smem stride: conflict-free fragment loads */

// ---------------- device scratch ----------------
__device__ float g_img[PP*BB*DD];
__device__ float g_txt[PP*BB*DD];
__device__ float g_fn2[PP*BB];
__device__ float g_cn2[PP*NN];
__device__ float g_imgsim[PP*BB*BB];
__device__ float g_txtsim[PP*BB*BB];
__device__ unsigned char g_negmask[NN];
__device__ float g_partial[PP*NTILES*BB];
__device__ float g_negsum[PP*BB];
__device__ float g_possum[PP*BB];
__device__ float g_alignpart[PP];

// ---------------- helpers ----------------
__device__ __forceinline__ float blockReduceSum(float v) {
    __shared__ float sh[32];
    int lane = threadIdx.x & 31, w = threadIdx.x >> 5;
    #pragma unroll
    for (int o = 16; o; o >>= 1) v += __shfl_down_sync(0xffffffffu, v, o);
    if (!lane) sh[w] = v;
    __syncthreads();
    int nw = (blockDim.x + 31) >> 5;
    v = (threadIdx.x < nw) ? sh[threadIdx.x] : 0.f;
    if (!w) {
        #pragma unroll
        for (int o = 16; o; o >>= 1) v += __shfl_down_sync(0xffffffffu, v, o);
    }
    __syncthreads();
    return v;  // valid on thread 0
}

__device__ __forceinline__ float tf32r(float x) {
    asm("cvt.rna.tf32.f32 %0, %0;" : "+f"(x));
    return x;
}

__device__ __forceinline__ void mma_tf32(float* c, const uint32_t* a, const uint32_t* b) {
    asm volatile(
        "mma.sync.aligned.m16n8k8.row.col.f32.tf32.tf32.f32 "
        "{%0,%1,%2,%3}, {%4,%5,%6,%7}, {%8,%9}, {%0,%1,%2,%3};\n"
        : "+f"(c[0]), "+f"(c[1]), "+f"(c[2]), "+f"(c[3])
        : "r"(a[0]), "r"(a[1]), "r"(a[2]), "r"(a[3]), "r"(b[0]), "r"(b[1]));
}

// ---------------- 1. normalize rows + fn2 ----------------
__global__ void prep_kernel(const float* __restrict__ feat,
                            const float* __restrict__ text) {
    int pb = blockIdx.x;
    int p = pb / BB, b = pb % BB;
    const float* f = feat + (size_t)pb * DD;
    const float* t = text + ((size_t)b * PP + p) * DD;
    float s1 = 0.f, s2 = 0.f;
    for (int d = threadIdx.x; d < DD; d += 128) {
        float v = f[d]; s1 += v * v;
        float w = t[d]; s2 += w * w;
    }
    __shared__ float inv1, inv2;
    float r1 = blockReduceSum(s1);
    if (threadIdx.x == 0) {
        g_fn2[pb] = r1;
        inv1 = 1.f / fmaxf(sqrtf(r1), 1e-12f);
    }
    float r2 = blockReduceSum(s2);
    if (threadIdx.x == 0) inv2 = 1.f / fmaxf(sqrtf(r2), 1e-12f);
    __syncthreads();
    for (int d = threadIdx.x; d < DD; d += 128) {
        g_img[(size_t)pb * DD + d] = f[d] * inv1;
        g_txt[(size_t)pb * DD + d] = t[d] * inv2;
    }
}

// ---------------- 2. neg mask ----------------
__global__ void mask_init_kernel() {
    int i = blockIdx.x * 256 + threadIdx.x;
    if (i < NN) g_negmask[i] = 1;
}
__global__ void mask_scatter_kernel(const int* __restrict__ ci,
                                    const int* __restrict__ pos) {
    int i = blockIdx.x * 256 + threadIdx.x;
    if (i < BB * KK)            g_negmask[ci[i]] = 0;
    else if (i < BB * KK + BB)  g_negmask[pos[i - BB * KK]] = 0;
}

// ---------------- 3. tensor-core GEMM (tf32 mma.sync), 128x128x512 per block --------
// NEG=true : grid (NTILES, P); A = feature[p], B = centers[p] tile; epilogue =
//            masked exp-dist row sums + fused cn2.
// NEG=false: grid (2, P); A = B = normalized img/txt; epilogue stores sim*2.
template<bool NEG>
__global__ __launch_bounds__(256) void mma_gemm_kernel(
        const float* __restrict__ feat, const float* __restrict__ centers) {
    int p = blockIdx.y;
    const float* Aptr;
    const float* Bptr;
    float* simdst = nullptr;
    int n0 = 0;
    if (NEG) {
        n0 = blockIdx.x * NT;
        Aptr = feat + (size_t)p * BB * DD;
        Bptr = centers + ((size_t)p * NN + n0) * DD;
    } else {
        const float* src = (blockIdx.x ? g_txt : g_img) + (size_t)p * BB * DD;
        Aptr = src; Bptr = src;
        simdst = (blockIdx.x ? g_txtsim : g_imgsim) + (size_t)p * BB * BB;
    }

    __shared__ float As[2][16][SA];
    __shared__ float Bs[2][16][SA];
    __shared__ float redp[4][BB];
    __shared__ float cn2s[BB];

    int t = threadIdx.x;
    int lane = t & 31, wid = t >> 5;
    int g = lane >> 2, tig = lane & 3;
    int warpM = (wid >> 2) * 64;   // 0 or 64
    int warpN = (wid & 3) * 32;    // 0,32,64,96

    int srow = t >> 1;             // staging row (m for A, n for B)
    int kh = t & 1;                // k half within 16-chunk
    const float* ga = Aptr + (size_t)srow * DD + kh * 8;
    const float* gb = Bptr + (size_t)srow * DD + kh * 8;

    float acc[4][4][4];
    #pragma unroll
    for (int i = 0; i < 4; i++)
        #pragma unroll
        for (int j = 0; j < 4; j++)
            #pragma unroll
            for (int q = 0; q < 4; q++) acc[i][j][q] = 0.f;

    float csq = 0.f;

    // prologue: stage chunk 0
    float4 av0 = *(const float4*)(ga);
    float4 av1 = *(const float4*)(ga + 4);
    float4 bv0 = *(const float4*)(gb);
    float4 bv1 = *(const float4*)(gb + 4);
    {
        int kb = kh * 8;
        As[0][kb+0][srow]=tf32r(av0.x); As[0][kb+1][srow]=tf32r(av0.y);
        As[0][kb+2][srow]=tf32r(av0.z); As[0][kb+3][srow]=tf32r(av0.w);
        As[0][kb+4][srow]=tf32r(av1.x); As[0][kb+5][srow]=tf32r(av1.y);
        As[0][kb+6][srow]=tf32r(av1.z); As[0][kb+7][srow]=tf32r(av1.w);
        Bs[0][kb+0][srow]=tf32r(bv0.x); Bs[0][kb+1][srow]=tf32r(bv0.y);
        Bs[0][kb+2][srow]=tf32r(bv0.z); Bs[0][kb+3][srow]=tf32r(bv0.w);
        Bs[0][kb+4][srow]=tf32r(bv1.x); Bs[0][kb+5][srow]=tf32r(bv1.y);
        Bs[0][kb+6][srow]=tf32r(bv1.z); Bs[0][kb+7][srow]=tf32r(bv1.w);
        if (NEG) {
            csq += bv0.x*bv0.x + bv0.y*bv0.y + bv0.z*bv0.z + bv0.w*bv0.w;
            csq += bv1.x*bv1.x + bv1.y*bv1.y + bv1.z*bv1.z + bv1.w*bv1.w;
        }
    }
    __syncthreads();

    for (int c = 0; c < 32; c++) {
        int buf = c & 1;
        if (c < 31) {
            const float* ga2 = ga + (c + 1) * 16;
            const float* gb2 = gb + (c + 1) * 16;
            av0 = *(const float4*)(ga2);
            av1 = *(const float4*)(ga2 + 4);
            bv0 = *(const float4*)(gb2);
            bv1 = *(const float4*)(gb2 + 4);
        }
        // compute two k8 steps on buf
        #pragma unroll
        for (int ks = 0; ks < 2; ks++) {
            int kb = ks * 8;
            uint32_t af[4][4], bf[4][2];
            #pragma unroll
            for (int mt = 0; mt < 4; mt++) {
                int r0 = warpM + mt * 16 + g;
                af[mt][0] = __float_as_uint(As[buf][kb+tig  ][r0]);
                af[mt][1] = __float_as_uint(As[buf][kb+tig  ][r0+8]);
                af[mt][2] = __float_as_uint(As[buf][kb+tig+4][r0]);
                af[mt][3] = __float_as_uint(As[buf][kb+tig+4][r0+8]);
            }
            #pragma unroll
            for (int nt = 0; nt < 4; nt++) {
                int cc = warpN + nt * 8 + g;
                bf[nt][0] = __float_as_uint(Bs[buf][kb+tig  ][cc]);
                bf[nt][1] = __float_as_uint(Bs[buf][kb+tig+4][cc]);
            }
            #pragma unroll
            for (int mt = 0; mt < 4; mt++)
                #pragma unroll
                for (int nt = 0; nt < 4; nt++)
                    mma_tf32(acc[mt][nt], af[mt], bf[nt]);
        }
        if (c < 31) {
            int nbuf = buf ^ 1;
            int kb = kh * 8;
            As[nbuf][kb+0][srow]=tf32r(av0.x); As[nbuf][kb+1][srow]=tf32r(av0.y);
            As[nbuf][kb+2][srow]=tf32r(av0.z); As[nbuf][kb+3][srow]=tf32r(av0.w);
            As[nbuf][kb+4][srow]=tf32r(av1.x); As[nbuf][kb+5][srow]=tf32r(av1.y);
            As[nbuf][kb+6][srow]=tf32r(av1.z); As[nbuf][kb+7][srow]=tf32r(av1.w);
            Bs[nbuf][kb+0][srow]=tf32r(bv0.x); Bs[nbuf][kb+1][srow]=tf32r(bv0.y);
            Bs[nbuf][kb+2][srow]=tf32r(bv0.z); Bs[nbuf][kb+3][srow]=tf32r(bv0.w);
            Bs[nbuf][kb+4][srow]=tf32r(bv1.x); Bs[nbuf][kb+5][srow]=tf32r(bv1.y);
            Bs[nbuf][kb+6][srow]=tf32r(bv1.z); Bs[nbuf][kb+7][srow]=tf32r(bv1.w);
            if (NEG) {
                csq += bv0.x*bv0.x + bv0.y*bv0.y + bv0.z*bv0.z + bv0.w*bv0.w;
                csq += bv1.x*bv1.x + bv1.y*bv1.y + bv1.z*bv1.z + bv1.w*bv1.w;
            }
        }
        __syncthreads();
    }

    if (NEG) {
        // finalize fused cn2 (lanes 2j/2j+1 hold the two k-halves of row srow)
        csq += __shfl_xor_sync(0xffffffffu, csq, 1);
        if (kh == 0) {
            cn2s[srow] = csq;
            g_cn2[(size_t)p * NN + n0 + srow] = csq;
        }
        __syncthreads();

        float rsum[4][2];
        #pragma unroll
        for (int mt = 0; mt < 4; mt++) { rsum[mt][0] = 0.f; rsum[mt][1] = 0.f; }

        float f0[4], f1[4];
        #pragma unroll
        for (int mt = 0; mt < 4; mt++) {
            f0[mt] = g_fn2[p * BB + warpM + mt * 16 + g];
            f1[mt] = g_fn2[p * BB + warpM + mt * 16 + g + 8];
        }
        #pragma unroll
        for (int nt = 0; nt < 4; nt++) {
            int c0 = warpN + nt * 8 + 2 * tig;
            int c1 = c0 + 1;
            bool m0 = g_negmask[n0 + c0] != 0;
            bool m1 = g_negmask[n0 + c1] != 0;
            float cn0 = cn2s[c0], cn1 = cn2s[c1];
            #pragma unroll
            for (int mt = 0; mt < 4; mt++) {
                if (m0) {
                    float pd2 = f0[mt] + cn0 - 2.f * acc[mt][nt][0];
                    rsum[mt][0] += __expf(-SCALE_C * sqrtf(fmaxf(pd2, 1e-12f)));
                    pd2 = f1[mt] + cn0 - 2.f * acc[mt][nt][2];
                    rsum[mt][1] += __expf(-SCALE_C * sqrtf(fmaxf(pd2, 1e-12f)));
                }
                if (m1) {
                    float pd2 = f0[mt] + cn1 - 2.f * acc[mt][nt][1];
                    rsum[mt][0] += __expf(-SCALE_C * sqrtf(fmaxf(pd2, 1e-12f)));
                    pd2 = f1[mt] + cn1 - 2.f * acc[mt][nt][3];
                    rsum[mt][1] += __expf(-SCALE_C * sqrtf(fmaxf(pd2, 1e-12f)));
                }
            }
        }
        // reduce across tig (4 lanes share the same rows)
        #pragma unroll
        for (int mt = 0; mt < 4; mt++) {
            #pragma unroll
            for (int h = 0; h < 2; h++) {
                float v = rsum[mt][h];
                v += __shfl_xor_sync(0xffffffffu, v, 1);
                v += __shfl_xor_sync(0xffffffffu, v, 2);
                rsum[mt][h] = v;
            }
        }
        if (tig == 0) {
            #pragma unroll
            for (int mt = 0; mt < 4; mt++) {
                redp[wid & 3][warpM + mt * 16 + g]     = rsum[mt][0];
                redp[wid & 3][warpM + mt * 16 + g + 8] = rsum[mt][1];
            }
        }
        __syncthreads();
        if (t < BB) {
            float s = redp[0][t] + redp[1][t] + redp[2][t] + redp[3][t];
            g_partial[((size_t)p * NTILES + blockIdx.x) * BB + t] = s;
        }
    } else {
        // sim epilogue: dst = dot * (1/TEMP)
        #pragma unroll
        for (int mt = 0; mt < 4; mt++) {
            int r0 = warpM + mt * 16 + g;
            int r1 = r0 + 8;
            #pragma unroll
            for (int nt = 0; nt < 4; nt++) {
                int c0 = warpN + nt * 8 + 2 * tig;
                simdst[r0 * BB + c0]     = acc[mt][nt][0] * INV_TEMP;
                simdst[r0 * BB + c0 + 1] = acc[mt][nt][1] * INV_TEMP;
                simdst[r1 * BB + c0]     = acc[mt][nt][2] * INV_TEMP;
                simdst[r1 * BB + c0 + 1] = acc[mt][nt][3] * INV_TEMP;
            }
        }
    }
}

// ---------------- 4. reduce partials -> negsum ----------------
__global__ void neg_reduce_kernel() {
    int pb = blockIdx.x;
    int p = pb / BB, b = pb % BB;
    float s = g_partial[((size_t)p * NTILES + threadIdx.x) * BB + b];
    float r = blockReduceSum(s);
    if (threadIdx.x == 0) g_negsum[pb] = r;
}

// ---------------- 5. positive distances ----------------
__global__ void pos_kernel(const float* __restrict__ feat,
                           const float* __restrict__ centers,
                           const int* __restrict__ ci) {
    int pb = blockIdx.x;
    int p = pb / BB, b = pb % BB;
    int lane = threadIdx.x;
    const float4* f = (const float4*)(feat + (size_t)pb * DD);
    float fn2v = g_fn2[pb];
    float possum = 0.f;
    for (int k = 0; k < KK; k++) {
        int idx = ci[b * KK + k];
        const float4* c = (const float4*)(centers + ((size_t)p * NN + idx) * DD);
        float dot = 0.f;
        #pragma unroll
        for (int q = lane; q < DD / 4; q += 32) {
            float4 a = f[q], bv = c[q];
            dot += a.x * bv.x + a.y * bv.y + a.z * bv.z + a.w * bv.w;
        }
        #pragma unroll
        for (int o = 16; o; o >>= 1) dot += __shfl_down_sync(0xffffffffu, dot, o);
        if (lane == 0) {
            float pn2 = g_cn2[(size_t)p * NN + idx];
            float pd2 = fn2v + pn2 - 2.f * dot;
            possum += expf(-SCALE_C * sqrtf(fmaxf(pd2, 1e-12f)));
        }
    }
    if (lane == 0) g_possum[pb] = possum;
}

// ---------------- 6. align / KL loss ----------------
__global__ void align_kernel() {
    int p = blockIdx.x;
    int b = threadIdx.x;
    const float* imrow = g_imgsim + ((size_t)p * BB + b) * BB;
    const float* txrow = g_txtsim + ((size_t)p * BB + b) * BB;
    __shared__ unsigned char shv[BB];
    bool v = false;
    for (int c = 0; c < BB; c++)
        if (imrow[c] > SIM_THR && txrow[c] > SIM_THR) v = true;
    shv[b] = v ? 1 : 0;
    __syncthreads();

    float mi = NEG_INF_F, mt = NEG_INF_F;
    for (int c = 0; c < BB; c++)
        if (shv[c]) { mi = fmaxf(mi, imrow[c]); mt = fmaxf(mt, txrow[c]); }
    float si = 0.f, st = 0.f;
    for (int c = 0; c < BB; c++)
        if (shv[c]) { si += expf(imrow[c] - mi); st += expf(txrow[c] - mt); }
    float lsei = logf(si) + mi;
    float lset = logf(st) + mt;
    float kl1 = 0.f, kl2 = 0.f;
    for (int c = 0; c < BB; c++) {
        if (shv[c]) {
            float ilp = imrow[c] - lsei;
            float tlp = txrow[c] - lset;
            kl1 += expf(tlp) * (tlp - ilp);
            kl2 += expf(ilp) * (ilp - tlp);
        }
    }
    float c1 = v ? kl1 : 0.f;
    float c2 = v ? kl2 : 0.f;
    float nvf = v ? 1.f : 0.f;
    float r1 = blockReduceSum(c1);
    __shared__ float sr1;
    if (b == 0) sr1 = r1;
    float r2 = blockReduceSum(c2);
    __shared__ float sr2;
    if (b == 0) sr2 = r2;
    float nv = blockReduceSum(nvf);
    if (b == 0) {
        int n = (int)(nv + 0.5f);
        float per = (n > 0) ? 0.5f * (sr1 + sr2) / (float)max(n, 1) : 0.f;
        g_alignpart[p] = per;
    }
}

// ---------------- 7. final combine ----------------
__global__ void final_kernel(float* __restrict__ out) {
    int b = threadIdx.x;
    __shared__ float sacc;
    if (b == 0) sacc = 0.f;
    __syncthreads();
    for (int p = 0; p < PP; p++) {
        float v = logf(g_negsum[p * BB + b]) - logf(g_possum[p * BB + b]);
        float r = blockReduceSum(v);
        if (b == 0) {
            float lp = r / (float)BB;
            if (isnan(lp)) lp = 0.f;
            sacc += lp;
        }
        __syncthreads();
    }
    if (b == 0) {
        float contrastive = sacc / (float)PP;
        float align = g_alignpart[0] + g_alignpart[1] + g_alignpart[2] + g_alignpart[3];
        out[0] = contrastive + KLW * align;
        out[1] = contrastive;
        out[2] = align;
    }
}

// ---------------- 8. pos_vid gather ----------------
__global__ void posvid_kernel(const int* __restrict__ vid,
                              const int* __restrict__ ci,
                              float* __restrict__ out) {
    int i = blockIdx.x * 256 + threadIdx.x;
    if (i < BB * KK) out[3 + i] = (float)vid[ci[i]];
}

// ---------------- launch ----------------
extern "C" void kernel_launch(void* const* d_in, const int* in_sizes, int n_in,
                              void* d_out, int out_size) {
    const float* feature = (const float*)d_in[0];
    const float* text    = (const float*)d_in[1];
    const float* centers = (const float*)d_in[2];
    const int*   pos     = (const int*)d_in[3];
    const int*   ci      = (const int*)d_in[4];
    const int*   vid     = (const int*)d_in[5];
    float* out = (float*)d_out;

    prep_kernel<<<PP * BB, 128>>>(feature, text);
    mask_init_kernel<<<NN / 256, 256>>>();
    mask_scatter_kernel<<<(BB * KK + BB + 255) / 256, 256>>>(ci, pos);
    mma_gemm_kernel<true><<<dim3(NTILES, PP), 256>>>(feature, centers);
    neg_reduce_kernel<<<PP * BB, 256>>>();
    pos_kernel<<<PP * BB, 32>>>(feature, centers, ci);
    mma_gemm_kernel<false><<<dim3(2, PP), 256>>>(feature, centers);
    align_kernel<<<PP, 128>>>();
    final_kernel<<<1, 128>>>(out);
    posvid_kernel<<<(BB * KK + 255) / 256, 256>>>(vid, ci, out);
}

// round 10
// speedup vs baseline: 2.5622x; 1.1923x over previous
#include <cuda_runtime.h>
#include <math.h>
#include <stdint.h>

#define PP 4
#define BB 128
#define DD 512
#define NN 32768
#define KK 10
#define NT 128
#define NTILES (NN/NT)   /* 256 */
#define SCALE_C 10.0f
#define INV_TEMP 2.0f
#define SIM_THR 0.7f
#define KLW 0.4916666666666667f
#define NEG_INF_F (-1e30f)
#define RS 20            /* row stride in floats: conflict-free ldmatrix */
#define STAGE_F (BB*RS)  /* floats per stage per matrix */

// ---------------- device scratch ----------------
__device__ float g_img[PP*BB*DD];
__device__ float g_txt[PP*BB*DD];
__device__ float g_fn2[PP*BB];
__device__ float g_imgsim[PP*BB*BB];
__device__ float g_txtsim[PP*BB*BB];
__device__ unsigned char g_negmask[NN];
__device__ float g_partial[PP*NTILES*BB];
__device__ float g_negsum[PP*BB];
__device__ float g_possum[PP*BB];
__device__ float g_alignpart[PP];

// ---------------- helpers ----------------
__device__ __forceinline__ float blockReduceSum(float v) {
    __shared__ float sh[32];
    int lane = threadIdx.x & 31, w = threadIdx.x >> 5;
    #pragma unroll
    for (int o = 16; o; o >>= 1) v += __shfl_down_sync(0xffffffffu, v, o);
    if (!lane) sh[w] = v;
    __syncthreads();
    int nw = (blockDim.x + 31) >> 5;
    v = (threadIdx.x < nw) ? sh[threadIdx.x] : 0.f;
    if (!w) {
        #pragma unroll
        for (int o = 16; o; o >>= 1) v += __shfl_down_sync(0xffffffffu, v, o);
    }
    __syncthreads();
    return v;  // valid on thread 0
}

__device__ __forceinline__ float tf32r(float x) {
    asm("cvt.rna.tf32.f32 %0, %0;" : "+f"(x));
    return x;
}

__device__ __forceinline__ uint32_t smem_u32(const void* p) {
    uint32_t a;
    asm("{ .reg .u64 t; cvta.to.shared.u64 t, %1; cvt.u32.u64 %0, t; }"
        : "=r"(a) : "l"(p));
    return a;
}

__device__ __forceinline__ void cp16(uint32_t dst, const float* src) {
    asm volatile("cp.async.cg.shared.global [%0], [%1], 16;\n" :: "r"(dst), "l"(src));
}

__device__ __forceinline__ void ldsm4(uint32_t* r, uint32_t addr) {
    asm volatile("ldmatrix.sync.aligned.m8n8.x4.shared.b16 {%0,%1,%2,%3}, [%4];\n"
                 : "=r"(r[0]), "=r"(r[1]), "=r"(r[2]), "=r"(r[3]) : "r"(addr));
}

__device__ __forceinline__ void mma_tf32(float* c, const uint32_t* a, const uint32_t* b) {
    asm volatile(
        "mma.sync.aligned.m16n8k8.row.col.f32.tf32.tf32.f32 "
        "{%0,%1,%2,%3}, {%4,%5,%6,%7}, {%8,%9}, {%0,%1,%2,%3};\n"
        : "+f"(c[0]), "+f"(c[1]), "+f"(c[2]), "+f"(c[3])
        : "r"(a[0]), "r"(a[1]), "r"(a[2]), "r"(a[3]), "r"(b[0]), "r"(b[1]));
}

// ---------------- 1. normalize rows + fn2 + negmask init ----------------
// g_img/g_txt are stored ALREADY ROUNDED to tf32 (RNA) so the sim GEMM's
// in-HW truncation is a no-op -> unbiased sims (the 0.7 threshold mask is
// bias-sensitive).
__global__ void prep_kernel(const float* __restrict__ feat,
                            const float* __restrict__ text) {
    int mi = blockIdx.x * 128 + threadIdx.x;
    if (mi < NN) g_negmask[mi] = 1;

    int pb = blockIdx.x;
    int p = pb / BB, b = pb % BB;
    const float* f = feat + (size_t)pb * DD;
    const float* t = text + ((size_t)b * PP + p) * DD;
    float s1 = 0.f, s2 = 0.f;
    for (int d = threadIdx.x; d < DD; d += 128) {
        float v = f[d]; s1 += v * v;
        float w = t[d]; s2 += w * w;
    }
    __shared__ float inv1, inv2;
    float r1 = blockReduceSum(s1);
    if (threadIdx.x == 0) {
        g_fn2[pb] = r1;
        inv1 = 1.f / fmaxf(sqrtf(r1), 1e-12f);
    }
    float r2 = blockReduceSum(s2);
    if (threadIdx.x == 0) inv2 = 1.f / fmaxf(sqrtf(r2), 1e-12f);
    __syncthreads();
    for (int d = threadIdx.x; d < DD; d += 128) {
        g_img[(size_t)pb * DD + d] = tf32r(f[d] * inv1);
        g_txt[(size_t)pb * DD + d] = tf32r(t[d] * inv2);
    }
}

// ---------------- 2. neg mask scatter ----------------
__global__ void mask_scatter_kernel(const int* __restrict__ ci,
                                    const int* __restrict__ pos) {
    int i = blockIdx.x * 256 + threadIdx.x;
    if (i < BB * KK)            g_negmask[ci[i]] = 0;
    else if (i < BB * KK + BB)  g_negmask[pos[i - BB * KK]] = 0;
}

// ---------------- 3. tensor-core GEMM: cp.async + ldmatrix ----------------
// NEG=true : grid (NTILES, P); epilogue = masked exp-dist row sums (cn2 fused
//            from smem re-read). NEG=false: grid (2, P); writes sim * 2.
template<bool NEG>
__global__ __launch_bounds__(256) void mma_gemm_kernel(
        const float* __restrict__ feat, const float* __restrict__ centers) {
    int p = blockIdx.y;
    const float* Aptr;
    const float* Bptr;
    float* simdst = nullptr;
    int n0 = 0;
    if (NEG) {
        n0 = blockIdx.x * NT;
        Aptr = feat + (size_t)p * BB * DD;
        Bptr = centers + ((size_t)p * NN + n0) * DD;
    } else {
        const float* src = (blockIdx.x ? g_txt : g_img) + (size_t)p * BB * DD;
        Aptr = src; Bptr = src;
        simdst = (blockIdx.x ? g_txtsim : g_imgsim) + (size_t)p * BB * BB;
    }

    __shared__ __align__(16) float As[2][STAGE_F];   // [stage][row*RS + k]
    __shared__ __align__(16) float Bs[2][STAGE_F];
    __shared__ float redp[4][BB];
    __shared__ float cn2s[BB];

    int t = threadIdx.x;
    int lane = t & 31, wid = t >> 5;
    int g = lane >> 2, tig = lane & 3;
    int warpM = (wid >> 2) * 64;
    int warpN = (wid & 3) * 32;
    int q = lane >> 3, r = lane & 7;

    uint32_t sA = smem_u32(As), sB = smem_u32(Bs);
    // ldmatrix per-lane row addresses (bytes)
    uint32_t aRM = sA + (((warpM + (q & 1) * 8 + r) * RS + (q >> 1) * 4) << 2);
    uint32_t bRM = sB + (((warpN + (q >> 1) * 8 + r) * RS + (q & 1) * 4) << 2);

    // staging addresses
    int srow = t >> 1, kh = t & 1;
    uint32_t dA = sA + ((srow * RS + kh * 8) << 2);
    uint32_t dB = sB + ((srow * RS + kh * 8) << 2);
    const float* gA = Aptr + (size_t)srow * DD + kh * 8;
    const float* gB = Bptr + (size_t)srow * DD + kh * 8;

    float acc[4][4][4];
    #pragma unroll
    for (int i = 0; i < 4; i++)
        #pragma unroll
        for (int j = 0; j < 4; j++)
            #pragma unroll
            for (int z = 0; z < 4; z++) acc[i][j][z] = 0.f;

    float csq = 0.f;
    const float* csrc = (const float*)&Bs[0][srow * RS + kh * 8];
    const float* csrc1 = (const float*)&Bs[1][srow * RS + kh * 8];

    // prologue: stage chunk 0 into stage 0
    cp16(dA, gA); cp16(dA + 16, gA + 4);
    cp16(dB, gB); cp16(dB + 16, gB + 4);
    asm volatile("cp.async.commit_group;\n");

    for (int c = 0; c < 32; c++) {
        int buf = c & 1;
        if (c < 31) {
            uint32_t off = (uint32_t)((buf ^ 1) * STAGE_F) << 2;
            const float* gA2 = gA + (c + 1) * 16;
            const float* gB2 = gB + (c + 1) * 16;
            cp16(dA + off, gA2); cp16(dA + off + 16, gA2 + 4);
            cp16(dB + off, gB2); cp16(dB + off + 16, gB2 + 4);
            asm volatile("cp.async.commit_group;\n");
            asm volatile("cp.async.wait_group 1;\n");
        } else {
            asm volatile("cp.async.wait_group 0;\n");
        }
        __syncthreads();

        if (NEG) {  // fused cn2 accumulation from smem
            const float4* cb = (const float4*)(buf ? csrc1 : csrc);
            float4 v0 = cb[0], v1 = cb[1];
            csq += v0.x*v0.x + v0.y*v0.y + v0.z*v0.z + v0.w*v0.w
                 + v1.x*v1.x + v1.y*v1.y + v1.z*v1.z + v1.w*v1.w;
        }

        uint32_t soff = (uint32_t)(buf * STAGE_F) << 2;
        #pragma unroll
        for (int ks = 0; ks < 2; ks++) {
            uint32_t koff = soff + ks * 32;
            uint32_t af[4][4], bf[4][2];
            #pragma unroll
            for (int mt = 0; mt < 4; mt++)
                ldsm4(af[mt], aRM + koff + mt * (16 * RS * 4));
            {
                uint32_t tmp[4];
                ldsm4(tmp, bRM + koff);
                bf[0][0]=tmp[0]; bf[0][1]=tmp[1]; bf[1][0]=tmp[2]; bf[1][1]=tmp[3];
                ldsm4(tmp, bRM + koff + 16 * RS * 4);
                bf[2][0]=tmp[0]; bf[2][1]=tmp[1]; bf[3][0]=tmp[2]; bf[3][1]=tmp[3];
            }
            #pragma unroll
            for (int mt = 0; mt < 4; mt++)
                #pragma unroll
                for (int nt = 0; nt < 4; nt++)
                    mma_tf32(acc[mt][nt], af[mt], bf[nt]);
        }
        __syncthreads();
    }

    if (NEG) {
        csq += __shfl_xor_sync(0xffffffffu, csq, 1);
        if (kh == 0) cn2s[srow] = csq;
        __syncthreads();

        float rsum[4][2];
        #pragma unroll
        for (int mt = 0; mt < 4; mt++) { rsum[mt][0] = 0.f; rsum[mt][1] = 0.f; }

        float f0[4], f1[4];
        #pragma unroll
        for (int mt = 0; mt < 4; mt++) {
            f0[mt] = g_fn2[p * BB + warpM + mt * 16 + g];
            f1[mt] = g_fn2[p * BB + warpM + mt * 16 + g + 8];
        }
        #pragma unroll
        for (int nt = 0; nt < 4; nt++) {
            int c0 = warpN + nt * 8 + 2 * tig;
            int c1 = c0 + 1;
            bool m0 = g_negmask[n0 + c0] != 0;
            bool m1 = g_negmask[n0 + c1] != 0;
            float cn0 = cn2s[c0], cn1 = cn2s[c1];
            #pragma unroll
            for (int mt = 0; mt < 4; mt++) {
                if (m0) {
                    float pd2 = f0[mt] + cn0 - 2.f * acc[mt][nt][0];
                    rsum[mt][0] += __expf(-SCALE_C * sqrtf(fmaxf(pd2, 1e-12f)));
                    pd2 = f1[mt] + cn0 - 2.f * acc[mt][nt][2];
                    rsum[mt][1] += __expf(-SCALE_C * sqrtf(fmaxf(pd2, 1e-12f)));
                }
                if (m1) {
                    float pd2 = f0[mt] + cn1 - 2.f * acc[mt][nt][1];
                    rsum[mt][0] += __expf(-SCALE_C * sqrtf(fmaxf(pd2, 1e-12f)));
                    pd2 = f1[mt] + cn1 - 2.f * acc[mt][nt][3];
                    rsum[mt][1] += __expf(-SCALE_C * sqrtf(fmaxf(pd2, 1e-12f)));
                }
            }
        }
        #pragma unroll
        for (int mt = 0; mt < 4; mt++) {
            #pragma unroll
            for (int h = 0; h < 2; h++) {
                float v = rsum[mt][h];
                v += __shfl_xor_sync(0xffffffffu, v, 1);
                v += __shfl_xor_sync(0xffffffffu, v, 2);
                rsum[mt][h] = v;
            }
        }
        if (tig == 0) {
            #pragma unroll
            for (int mt = 0; mt < 4; mt++) {
                redp[wid & 3][warpM + mt * 16 + g]     = rsum[mt][0];
                redp[wid & 3][warpM + mt * 16 + g + 8] = rsum[mt][1];
            }
        }
        __syncthreads();
        if (t < BB) {
            float s = redp[0][t] + redp[1][t] + redp[2][t] + redp[3][t];
            g_partial[((size_t)p * NTILES + blockIdx.x) * BB + t] = s;
        }
    } else {
        #pragma unroll
        for (int mt = 0; mt < 4; mt++) {
            int r0 = warpM + mt * 16 + g;
            int r1 = r0 + 8;
            #pragma unroll
            for (int nt = 0; nt < 4; nt++) {
                int c0 = warpN + nt * 8 + 2 * tig;
                simdst[r0 * BB + c0]     = acc[mt][nt][0] * INV_TEMP;
                simdst[r0 * BB + c0 + 1] = acc[mt][nt][1] * INV_TEMP;
                simdst[r1 * BB + c0]     = acc[mt][nt][2] * INV_TEMP;
                simdst[r1 * BB + c0 + 1] = acc[mt][nt][3] * INV_TEMP;
            }
        }
    }
}

// ---------------- 4. fused neg-reduce + positive distances ----------------
// grid P*B blocks of 128 threads
__global__ void reduce_pos_kernel(const float* __restrict__ feat,
                                  const float* __restrict__ centers,
                                  const int* __restrict__ ci) {
    int pb = blockIdx.x;
    int p = pb / BB, b = pb % BB;
    int t = threadIdx.x, lane = t & 31, wid = t >> 5;

    // neg reduce: 256 partials, 128 threads
    float s = g_partial[((size_t)p * NTILES + t) * BB + b]
            + g_partial[((size_t)p * NTILES + t + 128) * BB + b];
    float rneg = blockReduceSum(s);
    if (t == 0) g_negsum[pb] = rneg;

    // positive: warp w handles k = w, w+4, ...
    __shared__ float wsum[4];
    const float4* f = (const float4*)(feat + (size_t)pb * DD);
    float fn2v = g_fn2[pb];
    float part = 0.f;
    for (int k = wid; k < KK; k += 4) {
        int idx = ci[b * KK + k];
        const float4* c = (const float4*)(centers + ((size_t)p * NN + idx) * DD);
        float dot = 0.f, pn2 = 0.f;
        #pragma unroll
        for (int qq = lane; qq < DD / 4; qq += 32) {
            float4 a = f[qq], bv = c[qq];
            dot += a.x * bv.x + a.y * bv.y + a.z * bv.z + a.w * bv.w;
            pn2 += bv.x * bv.x + bv.y * bv.y + bv.z * bv.z + bv.w * bv.w;
        }
        #pragma unroll
        for (int o = 16; o; o >>= 1) {
            dot += __shfl_down_sync(0xffffffffu, dot, o);
            pn2 += __shfl_down_sync(0xffffffffu, pn2, o);
        }
        if (lane == 0) {
            float pd2 = fn2v + pn2 - 2.f * dot;
            part += expf(-SCALE_C * sqrtf(fmaxf(pd2, 1e-12f)));
        }
    }
    if (lane == 0) wsum[wid] = part;
    __syncthreads();
    if (t == 0) g_possum[pb] = wsum[0] + wsum[1] + wsum[2] + wsum[3];
}

// ---------------- 5. align / KL loss ----------------
__global__ void align_kernel() {
    int p = blockIdx.x;
    int b = threadIdx.x;
    const float* imrow = g_imgsim + ((size_t)p * BB + b) * BB;
    const float* txrow = g_txtsim + ((size_t)p * BB + b) * BB;
    __shared__ unsigned char shv[BB];
    bool v = false;
    for (int c = 0; c < BB; c++)
        if (imrow[c] > SIM_THR && txrow[c] > SIM_THR) v = true;
    shv[b] = v ? 1 : 0;
    __syncthreads();

    float mi = NEG_INF_F, mt = NEG_INF_F;
    for (int c = 0; c < BB; c++)
        if (shv[c]) { mi = fmaxf(mi, imrow[c]); mt = fmaxf(mt, txrow[c]); }
    float si = 0.f, st = 0.f;
    for (int c = 0; c < BB; c++)
        if (shv[c]) { si += expf(imrow[c] - mi); st += expf(txrow[c] - mt); }
    float lsei = logf(si) + mi;
    float lset = logf(st) + mt;
    float kl1 = 0.f, kl2 = 0.f;
    for (int c = 0; c < BB; c++) {
        if (shv[c]) {
            float ilp = imrow[c] - lsei;
            float tlp = txrow[c] - lset;
            kl1 += expf(tlp) * (tlp - ilp);
            kl2 += expf(ilp) * (ilp - tlp);
        }
    }
    float c1 = v ? kl1 : 0.f;
    float c2 = v ? kl2 : 0.f;
    float nvf = v ? 1.f : 0.f;
    float r1 = blockReduceSum(c1);
    __shared__ float sr1;
    if (b == 0) sr1 = r1;
    float r2 = blockReduceSum(c2);
    __shared__ float sr2;
    if (b == 0) sr2 = r2;
    float nv = blockReduceSum(nvf);
    if (b == 0) {
        int n = (int)(nv + 0.5f);
        float per = (n > 0) ? 0.5f * (sr1 + sr2) / (float)max(n, 1) : 0.f;
        g_alignpart[p] = per;
    }
}

// ---------------- 6. final combine + pos_vid gather ----------------
__global__ void final_kernel(const int* __restrict__ vid,
                             const int* __restrict__ ci,
                             float* __restrict__ out) {
    int b = threadIdx.x;
    for (int i = b; i < BB * KK; i += 128) out[3 + i] = (float)vid[ci[i]];

    __shared__ float sacc;
    if (b == 0) sacc = 0.f;
    __syncthreads();
    for (int p = 0; p < PP; p++) {
        float v = logf(g_negsum[p * BB + b]) - logf(g_possum[p * BB + b]);
        float r = blockReduceSum(v);
        if (b == 0) {
            float lp = r / (float)BB;
            if (isnan(lp)) lp = 0.f;
            sacc += lp;
        }
        __syncthreads();
    }
    if (b == 0) {
        float contrastive = sacc / (float)PP;
        float align = g_alignpart[0] + g_alignpart[1] + g_alignpart[2] + g_alignpart[3];
        out[0] = contrastive + KLW * align;
        out[1] = contrastive;
        out[2] = align;
    }
}

// ---------------- launch ----------------
extern "C" void kernel_launch(void* const* d_in, const int* in_sizes, int n_in,
                              void* d_out, int out_size) {
    const float* feature = (const float*)d_in[0];
    const float* text    = (const float*)d_in[1];
    const float* centers = (const float*)d_in[2];
    const int*   pos     = (const int*)d_in[3];
    const int*   ci      = (const int*)d_in[4];
    const int*   vid     = (const int*)d_in[5];
    float* out = (float*)d_out;

    prep_kernel<<<PP * BB, 128>>>(feature, text);
    mask_scatter_kernel<<<(BB * KK + BB + 255) / 256, 256>>>(ci, pos);
    mma_gemm_kernel<true><<<dim3(NTILES, PP), 256>>>(feature, centers);
    mma_gemm_kernel<false><<<dim3(2, PP), 256>>>(feature, centers);
    reduce_pos_kernel<<<PP * BB, 128>>>(feature, centers, ci);
    align_kernel<<<PP, 128>>>();
    final_kernel<<<1, 128>>>(vid, ci, out);
}

// round 11
// speedup vs baseline: 2.6615x; 1.0387x over previous
#include <cuda_runtime.h>
#include <math.h>
#include <stdint.h>

#define PP 4
#define BB 128
#define DD 512
#define NN 32768
#define KK 10
#define NT 128
#define NTILES (NN/NT)   /* 256 */
#define SCALE_C 10.0f
#define INV_TEMP 2.0f
#define SIM_THR 0.7f
#define KLW 0.4916666666666667f
#define NEG_INF_F (-1e30f)
#define RS 20            /* row stride in floats: conflict-free ldmatrix */
#define STAGE_F (BB*RS)  /* floats per stage per matrix (2560) */
#define NSTG 4
#define DSMEM_BYTES (2*NSTG*STAGE_F*4)   /* 81920 */

// ---------------- device scratch ----------------
__device__ float g_img[PP*BB*DD];
__device__ float g_txt[PP*BB*DD];
__device__ float g_fn2[PP*BB];
__device__ float g_simpart[2*PP*4*BB*BB];
__device__ float g_imgsim[PP*BB*BB];
__device__ float g_txtsim[PP*BB*BB];
__device__ unsigned char g_negmask[NN];
__device__ float g_partial[PP*NTILES*BB];
__device__ float g_negsum[PP*BB];
__device__ float g_possum[PP*BB];
__device__ float g_alignpart[PP];

// ---------------- helpers ----------------
__device__ __forceinline__ float blockReduceSum(float v) {
    __shared__ float sh[32];
    int lane = threadIdx.x & 31, w = threadIdx.x >> 5;
    #pragma unroll
    for (int o = 16; o; o >>= 1) v += __shfl_down_sync(0xffffffffu, v, o);
    if (!lane) sh[w] = v;
    __syncthreads();
    int nw = (blockDim.x + 31) >> 5;
    v = (threadIdx.x < nw) ? sh[threadIdx.x] : 0.f;
    if (!w) {
        #pragma unroll
        for (int o = 16; o; o >>= 1) v += __shfl_down_sync(0xffffffffu, v, o);
    }
    __syncthreads();
    return v;  // valid on thread 0
}

__device__ __forceinline__ float tf32r(float x) {
    asm("cvt.rna.tf32.f32 %0, %0;" : "+f"(x));
    return x;
}

__device__ __forceinline__ uint32_t smem_u32(const void* p) {
    uint32_t a;
    asm("{ .reg .u64 t; cvta.to.shared.u64 t, %1; cvt.u32.u64 %0, t; }"
        : "=r"(a) : "l"(p));
    return a;
}

__device__ __forceinline__ void cp16(uint32_t dst, const float* src) {
    asm volatile("cp.async.cg.shared.global [%0], [%1], 16;\n" :: "r"(dst), "l"(src));
}

__device__ __forceinline__ void ldsm4(uint32_t* r, uint32_t addr) {
    asm volatile("ldmatrix.sync.aligned.m8n8.x4.shared.b16 {%0,%1,%2,%3}, [%4];\n"
                 : "=r"(r[0]), "=r"(r[1]), "=r"(r[2]), "=r"(r[3]) : "r"(addr));
}

__device__ __forceinline__ void mma_tf32(float* c, const uint32_t* a, const uint32_t* b) {
    asm volatile(
        "mma.sync.aligned.m16n8k8.row.col.f32.tf32.tf32.f32 "
        "{%0,%1,%2,%3}, {%4,%5,%6,%7}, {%8,%9}, {%0,%1,%2,%3};\n"
        : "+f"(c[0]), "+f"(c[1]), "+f"(c[2]), "+f"(c[3])
        : "r"(a[0]), "r"(a[1]), "r"(a[2]), "r"(a[3]), "r"(b[0]), "r"(b[1]));
}

// ---------------- 1. normalize rows + fn2 + negmask init ----------------
// g_img/g_txt stored ALREADY ROUNDED to tf32 (RNA) so the sim GEMM's in-HW
// truncation is a no-op -> unbiased sims (0.7 threshold mask is bias-sensitive).
__global__ void prep_kernel(const float* __restrict__ feat,
                            const float* __restrict__ text) {
    int mi = blockIdx.x * 128 + threadIdx.x;
    if (mi < NN) g_negmask[mi] = 1;

    int pb = blockIdx.x;
    int p = pb / BB, b = pb % BB;
    const float* f = feat + (size_t)pb * DD;
    const float* t = text + ((size_t)b * PP + p) * DD;
    float s1 = 0.f, s2 = 0.f;
    for (int d = threadIdx.x; d < DD; d += 128) {
        float v = f[d]; s1 += v * v;
        float w = t[d]; s2 += w * w;
    }
    __shared__ float inv1, inv2;
    float r1 = blockReduceSum(s1);
    if (threadIdx.x == 0) {
        g_fn2[pb] = r1;
        inv1 = 1.f / fmaxf(sqrtf(r1), 1e-12f);
    }
    float r2 = blockReduceSum(s2);
    if (threadIdx.x == 0) inv2 = 1.f / fmaxf(sqrtf(r2), 1e-12f);
    __syncthreads();
    for (int d = threadIdx.x; d < DD; d += 128) {
        g_img[(size_t)pb * DD + d] = tf32r(f[d] * inv1);
        g_txt[(size_t)pb * DD + d] = tf32r(t[d] * inv2);
    }
}

// ---------------- 2. neg mask scatter ----------------
__global__ void mask_scatter_kernel(const int* __restrict__ ci,
                                    const int* __restrict__ pos) {
    int i = blockIdx.x * 256 + threadIdx.x;
    if (i < BB * KK)            g_negmask[ci[i]] = 0;
    else if (i < BB * KK + BB)  g_negmask[pos[i - BB * KK]] = 0;
}

// ---------------- 3. tensor-core GEMM: 4-stage cp.async ring + ldmatrix ------
// NEG=true : grid (NTILES, P), NC=32 chunks; epilogue = masked exp-dist row
//            sums with cn2 fused from smem re-read.
// NEG=false: grid (8, P): bx = sel*4+kz, NC=8 chunks of the K range
//            [kz*128, kz*128+128); writes raw dot partials to g_simpart.
template<bool NEG>
__global__ __launch_bounds__(256) void mma_gemm_kernel(
        const float* __restrict__ feat, const float* __restrict__ centers) {
    extern __shared__ __align__(16) float dyn[];
    float* AsBase = dyn;                     // [NSTG][STAGE_F]
    float* BsBase = dyn + NSTG * STAGE_F;
    __shared__ float redp[4][BB];
    __shared__ float cn2s[BB];

    int p = blockIdx.y;
    const float* Aptr;
    const float* Bptr;
    float* partdst = nullptr;
    int n0 = 0;
    const int NC = NEG ? 32 : 8;
    if (NEG) {
        n0 = blockIdx.x * NT;
        Aptr = feat + (size_t)p * BB * DD;
        Bptr = centers + ((size_t)p * NN + n0) * DD;
    } else {
        int sel = blockIdx.x >> 2, kz = blockIdx.x & 3;
        const float* src = (sel ? g_txt : g_img) + (size_t)p * BB * DD + kz * 128;
        Aptr = src; Bptr = src;
        partdst = g_simpart + (size_t)((sel * PP + p) * 4 + kz) * BB * BB;
    }

    int t = threadIdx.x;
    int lane = t & 31, wid = t >> 5;
    int g = lane >> 2, tig = lane & 3;
    int warpM = (wid >> 2) * 64;
    int warpN = (wid & 3) * 32;
    int q = lane >> 3, r = lane & 7;

    uint32_t sA = smem_u32(AsBase), sB = smem_u32(BsBase);
    // ldmatrix per-lane row addresses (bytes), relative to stage base
    uint32_t aRM = sA + (((warpM + (q & 1) * 8 + r) * RS + (q >> 1) * 4) << 2);
    uint32_t bRM = sB + (((warpN + (q >> 1) * 8 + r) * RS + (q & 1) * 4) << 2);

    // staging addresses
    int srow = t >> 1, kh = t & 1;
    uint32_t dA = sA + ((srow * RS + kh * 8) << 2);
    uint32_t dB = sB + ((srow * RS + kh * 8) << 2);
    const float* gA = Aptr + (size_t)srow * DD + kh * 8;
    const float* gB = Bptr + (size_t)srow * DD + kh * 8;

    float acc[4][4][4];
    #pragma unroll
    for (int i = 0; i < 4; i++)
        #pragma unroll
        for (int j = 0; j < 4; j++)
            #pragma unroll
            for (int z = 0; z < 4; z++) acc[i][j][z] = 0.f;

    float csq = 0.f;

    // prologue: issue stages 0..2
    #pragma unroll
    for (int s = 0; s < NSTG - 1; s++) {
        uint32_t off = (uint32_t)(s * STAGE_F) << 2;
        const float* gA2 = gA + s * 16;
        const float* gB2 = gB + s * 16;
        cp16(dA + off, gA2); cp16(dA + off + 16, gA2 + 4);
        cp16(dB + off, gB2); cp16(dB + off + 16, gB2 + 4);
        asm volatile("cp.async.commit_group;\n");
    }

    for (int c = 0; c < NC; c++) {
        // commits at top = 3 + c; wait<=2 pending -> stage c arrived
        asm volatile("cp.async.wait_group 2;\n");
        __syncthreads();   // all warps done reading stage (c-1)%4, data visible

        if (c + NSTG - 1 < NC) {   // prefetch stage c+3 into ring slot (c+3)%4
            int s = c + NSTG - 1;
            uint32_t off = (uint32_t)((s & (NSTG - 1)) * STAGE_F) << 2;
            const float* gA2 = gA + s * 16;
            const float* gB2 = gB + s * 16;
            cp16(dA + off, gA2); cp16(dA + off + 16, gA2 + 4);
            cp16(dB + off, gB2); cp16(dB + off + 16, gB2 + 4);
        }
        asm volatile("cp.async.commit_group;\n");   // always commit (may be empty)

        int buf = c & (NSTG - 1);
        if (NEG) {  // fused cn2 accumulation from smem
            const float4* cb = (const float4*)(BsBase + buf * STAGE_F + srow * RS + kh * 8);
            float4 v0 = cb[0], v1 = cb[1];
            csq += v0.x*v0.x + v0.y*v0.y + v0.z*v0.z + v0.w*v0.w
                 + v1.x*v1.x + v1.y*v1.y + v1.z*v1.z + v1.w*v1.w;
        }

        uint32_t soff = (uint32_t)(buf * STAGE_F) << 2;
        #pragma unroll
        for (int ks = 0; ks < 2; ks++) {
            uint32_t koff = soff + ks * 32;
            uint32_t af[4][4], bf[4][2];
            #pragma unroll
            for (int mt = 0; mt < 4; mt++)
                ldsm4(af[mt], aRM + koff + mt * (16 * RS * 4));
            {
                uint32_t tmp[4];
                ldsm4(tmp, bRM + koff);
                bf[0][0]=tmp[0]; bf[0][1]=tmp[1]; bf[1][0]=tmp[2]; bf[1][1]=tmp[3];
                ldsm4(tmp, bRM + koff + 16 * RS * 4);
                bf[2][0]=tmp[0]; bf[2][1]=tmp[1]; bf[3][0]=tmp[2]; bf[3][1]=tmp[3];
            }
            #pragma unroll
            for (int mt = 0; mt < 4; mt++)
                #pragma unroll
                for (int nt = 0; nt < 4; nt++)
                    mma_tf32(acc[mt][nt], af[mt], bf[nt]);
        }
    }
    __syncthreads();

    if (NEG) {
        csq += __shfl_xor_sync(0xffffffffu, csq, 1);
        if (kh == 0) cn2s[srow] = csq;
        __syncthreads();

        float rsum[4][2];
        #pragma unroll
        for (int mt = 0; mt < 4; mt++) { rsum[mt][0] = 0.f; rsum[mt][1] = 0.f; }

        float f0[4], f1[4];
        #pragma unroll
        for (int mt = 0; mt < 4; mt++) {
            f0[mt] = g_fn2[p * BB + warpM + mt * 16 + g];
            f1[mt] = g_fn2[p * BB + warpM + mt * 16 + g + 8];
        }
        #pragma unroll
        for (int nt = 0; nt < 4; nt++) {
            int c0 = warpN + nt * 8 + 2 * tig;
            int c1 = c0 + 1;
            bool m0 = g_negmask[n0 + c0] != 0;
            bool m1 = g_negmask[n0 + c1] != 0;
            float cn0 = cn2s[c0], cn1 = cn2s[c1];
            #pragma unroll
            for (int mt = 0; mt < 4; mt++) {
                if (m0) {
                    float pd2 = f0[mt] + cn0 - 2.f * acc[mt][nt][0];
                    rsum[mt][0] += __expf(-SCALE_C * sqrtf(fmaxf(pd2, 1e-12f)));
                    pd2 = f1[mt] + cn0 - 2.f * acc[mt][nt][2];
                    rsum[mt][1] += __expf(-SCALE_C * sqrtf(fmaxf(pd2, 1e-12f)));
                }
                if (m1) {
                    float pd2 = f0[mt] + cn1 - 2.f * acc[mt][nt][1];
                    rsum[mt][0] += __expf(-SCALE_C * sqrtf(fmaxf(pd2, 1e-12f)));
                    pd2 = f1[mt] + cn1 - 2.f * acc[mt][nt][3];
                    rsum[mt][1] += __expf(-SCALE_C * sqrtf(fmaxf(pd2, 1e-12f)));
                }
            }
        }
        #pragma unroll
        for (int mt = 0; mt < 4; mt++) {
            #pragma unroll
            for (int h = 0; h < 2; h++) {
                float v = rsum[mt][h];
                v += __shfl_xor_sync(0xffffffffu, v, 1);
                v += __shfl_xor_sync(0xffffffffu, v, 2);
                rsum[mt][h] = v;
            }
        }
        if (tig == 0) {
            #pragma unroll
            for (int mt = 0; mt < 4; mt++) {
                redp[wid & 3][warpM + mt * 16 + g]     = rsum[mt][0];
                redp[wid & 3][warpM + mt * 16 + g + 8] = rsum[mt][1];
            }
        }
        __syncthreads();
        if (t < BB) {
            float s = redp[0][t] + redp[1][t] + redp[2][t] + redp[3][t];
            g_partial[((size_t)p * NTILES + blockIdx.x) * BB + t] = s;
        }
    } else {
        #pragma unroll
        for (int mt = 0; mt < 4; mt++) {
            int r0 = warpM + mt * 16 + g;
            int r1 = r0 + 8;
            #pragma unroll
            for (int nt = 0; nt < 4; nt++) {
                int c0 = warpN + nt * 8 + 2 * tig;
                partdst[r0 * BB + c0]     = acc[mt][nt][0];
                partdst[r0 * BB + c0 + 1] = acc[mt][nt][1];
                partdst[r1 * BB + c0]     = acc[mt][nt][2];
                partdst[r1 * BB + c0 + 1] = acc[mt][nt][3];
            }
        }
    }
}

// ---------------- 3b. combine sim K-split partials ----------------
// grid 2*PP blocks of 256 threads; float4 vectorized
__global__ void sim_combine_kernel() {
    int sp = blockIdx.x;                  // sel*PP + p
    int sel = sp >> 2, p = sp & 3;
    const float4* b0 = (const float4*)(g_simpart + (size_t)sp * 4 * BB * BB);
    const float4* b1 = b0 + (BB * BB / 4);
    const float4* b2 = b1 + (BB * BB / 4);
    const float4* b3 = b2 + (BB * BB / 4);
    float4* dst = (float4*)((sel ? g_txtsim : g_imgsim) + (size_t)p * BB * BB);
    for (int i = threadIdx.x; i < BB * BB / 4; i += 256) {
        float4 a = b0[i], b = b1[i], c = b2[i], d = b3[i];
        float4 o;
        o.x = (a.x + b.x + c.x + d.x) * INV_TEMP;
        o.y = (a.y + b.y + c.y + d.y) * INV_TEMP;
        o.z = (a.z + b.z + c.z + d.z) * INV_TEMP;
        o.w = (a.w + b.w + c.w + d.w) * INV_TEMP;
        dst[i] = o;
    }
}

// ---------------- 4. fused neg-reduce + positive distances ----------------
__global__ void reduce_pos_kernel(const float* __restrict__ feat,
                                  const float* __restrict__ centers,
                                  const int* __restrict__ ci) {
    int pb = blockIdx.x;
    int p = pb / BB, b = pb % BB;
    int t = threadIdx.x, lane = t & 31, wid = t >> 5;

    float s = g_partial[((size_t)p * NTILES + t) * BB + b]
            + g_partial[((size_t)p * NTILES + t + 128) * BB + b];
    float rneg = blockReduceSum(s);
    if (t == 0) g_negsum[pb] = rneg;

    __shared__ float wsum[4];
    const float4* f = (const float4*)(feat + (size_t)pb * DD);
    float fn2v = g_fn2[pb];
    float part = 0.f;
    for (int k = wid; k < KK; k += 4) {
        int idx = ci[b * KK + k];
        const float4* c = (const float4*)(centers + ((size_t)p * NN + idx) * DD);
        float dot = 0.f, pn2 = 0.f;
        #pragma unroll
        for (int qq = lane; qq < DD / 4; qq += 32) {
            float4 a = f[qq], bv = c[qq];
            dot += a.x * bv.x + a.y * bv.y + a.z * bv.z + a.w * bv.w;
            pn2 += bv.x * bv.x + bv.y * bv.y + bv.z * bv.z + bv.w * bv.w;
        }
        #pragma unroll
        for (int o = 16; o; o >>= 1) {
            dot += __shfl_down_sync(0xffffffffu, dot, o);
            pn2 += __shfl_down_sync(0xffffffffu, pn2, o);
        }
        if (lane == 0) {
            float pd2 = fn2v + pn2 - 2.f * dot;
            part += expf(-SCALE_C * sqrtf(fmaxf(pd2, 1e-12f)));
        }
    }
    if (lane == 0) wsum[wid] = part;
    __syncthreads();
    if (t == 0) g_possum[pb] = wsum[0] + wsum[1] + wsum[2] + wsum[3];
}

// ---------------- 5. align / KL loss ----------------
__global__ void align_kernel() {
    int p = blockIdx.x;
    int b = threadIdx.x;
    const float* imrow = g_imgsim + ((size_t)p * BB + b) * BB;
    const float* txrow = g_txtsim + ((size_t)p * BB + b) * BB;
    __shared__ unsigned char shv[BB];
    bool v = false;
    for (int c = 0; c < BB; c++)
        if (imrow[c] > SIM_THR && txrow[c] > SIM_THR) v = true;
    shv[b] = v ? 1 : 0;
    __syncthreads();

    float mi = NEG_INF_F, mt = NEG_INF_F;
    for (int c = 0; c < BB; c++)
        if (shv[c]) { mi = fmaxf(mi, imrow[c]); mt = fmaxf(mt, txrow[c]); }
    float si = 0.f, st = 0.f;
    for (int c = 0; c < BB; c++)
        if (shv[c]) { si += expf(imrow[c] - mi); st += expf(txrow[c] - mt); }
    float lsei = logf(si) + mi;
    float lset = logf(st) + mt;
    float kl1 = 0.f, kl2 = 0.f;
    for (int c = 0; c < BB; c++) {
        if (shv[c]) {
            float ilp = imrow[c] - lsei;
            float tlp = txrow[c] - lset;
            kl1 += expf(tlp) * (tlp - ilp);
            kl2 += expf(ilp) * (ilp - tlp);
        }
    }
    float c1 = v ? kl1 : 0.f;
    float c2 = v ? kl2 : 0.f;
    float nvf = v ? 1.f : 0.f;
    float r1 = blockReduceSum(c1);
    __shared__ float sr1;
    if (b == 0) sr1 = r1;
    float r2 = blockReduceSum(c2);
    __shared__ float sr2;
    if (b == 0) sr2 = r2;
    float nv = blockReduceSum(nvf);
    if (b == 0) {
        int n = (int)(nv + 0.5f);
        float per = (n > 0) ? 0.5f * (sr1 + sr2) / (float)max(n, 1) : 0.f;
        g_alignpart[p] = per;
    }
}

// ---------------- 6. final combine + pos_vid gather ----------------
__global__ void final_kernel(const int* __restrict__ vid,
                             const int* __restrict__ ci,
                             float* __restrict__ out) {
    int b = threadIdx.x;
    for (int i = b; i < BB * KK; i += 128) out[3 + i] = (float)vid[ci[i]];

    __shared__ float sacc;
    if (b == 0) sacc = 0.f;
    __syncthreads();
    for (int p = 0; p < PP; p++) {
        float v = logf(g_negsum[p * BB + b]) - logf(g_possum[p * BB + b]);
        float r = blockReduceSum(v);
        if (b == 0) {
            float lp = r / (float)BB;
            if (isnan(lp)) lp = 0.f;
            sacc += lp;
        }
        __syncthreads();
    }
    if (b == 0) {
        float contrastive = sacc / (float)PP;
        float align = g_alignpart[0] + g_alignpart[1] + g_alignpart[2] + g_alignpart[3];
        out[0] = contrastive + KLW * align;
        out[1] = contrastive;
        out[2] = align;
    }
}

// ---------------- launch ----------------
extern "C" void kernel_launch(void* const* d_in, const int* in_sizes, int n_in,
                              void* d_out, int out_size) {
    const float* feature = (const float*)d_in[0];
    const float* text    = (const float*)d_in[1];
    const float* centers = (const float*)d_in[2];
    const int*   pos     = (const int*)d_in[3];
    const int*   ci      = (const int*)d_in[4];
    const int*   vid     = (const int*)d_in[5];
    float* out = (float*)d_out;

    cudaFuncSetAttribute(mma_gemm_kernel<true>,
                         cudaFuncAttributeMaxDynamicSharedMemorySize, DSMEM_BYTES);
    cudaFuncSetAttribute(mma_gemm_kernel<false>,
                         cudaFuncAttributeMaxDynamicSharedMemorySize, DSMEM_BYTES);

    prep_kernel<<<PP * BB, 128>>>(feature, text);
    mask_scatter_kernel<<<(BB * KK + BB + 255) / 256, 256>>>(ci, pos);
    mma_gemm_kernel<true><<<dim3(NTILES, PP), 256, DSMEM_BYTES>>>(feature, centers);
    mma_gemm_kernel<false><<<dim3(8, PP), 256, DSMEM_BYTES>>>(feature, centers);
    sim_combine_kernel<<<2 * PP, 256>>>();
    reduce_pos_kernel<<<PP * BB, 128>>>(feature, centers, ci);
    align_kernel<<<PP, 128>>>();
    final_kernel<<<1, 128>>>(vid, ci, out);
}

// round 13
// speedup vs baseline: 2.7894x; 1.0481x over previous
#include <cuda_runtime.h>
#include <math.h>
#include <stdint.h>

#define PP 4
#define BB 128
#define DD 512
#define NN 32768
#define KK 10
#define NT 128
#define NTILES (NN/NT)   /* 256 */
#define SCALE_C 10.0f
#define INV_TEMP 2.0f
#define SIM_THR 0.7f
#define KLW 0.4916666666666667f
#define NEG_INF_F (-1e30f)

/* sim (tf32 legacy) geometry */
#define RS 20
#define STAGE_F (BB*RS)
#define NSTG 4
#define DSMEM_BYTES (2*NSTG*STAGE_F*4)   /* 81920 */

/* neg (bf16 legacy) geometry */
#define KCH 32                  /* K elements per chunk */
#define NCH (DD/KCH)            /* 16 chunks */
#define SRS 40                  /* smem row stride in bf16 (80 bytes) */
#define TILEB (BB*SRS*2)        /* 10240 bytes per matrix per stage */

// ---------------- device scratch ----------------
__device__ float g_img[PP*BB*DD];
__device__ float g_txt[PP*BB*DD];
__device__ float g_fn2[PP*BB];
__device__ float g_simpart[2*PP*4*BB*BB];
__device__ float g_imgsim[PP*BB*BB];
__device__ float g_txtsim[PP*BB*BB];
__device__ unsigned char g_negmask[NN];
__device__ float g_partial[PP*NTILES*BB];
__device__ float g_negsum[PP*BB];
__device__ float g_possum[PP*BB];
__device__ float g_alignpart[PP];

// ---------------- helpers ----------------
__device__ __forceinline__ float blockReduceSum(float v) {
    __shared__ float sh[32];
    int lane = threadIdx.x & 31, w = threadIdx.x >> 5;
    #pragma unroll
    for (int o = 16; o; o >>= 1) v += __shfl_down_sync(0xffffffffu, v, o);
    if (!lane) sh[w] = v;
    __syncthreads();
    int nw = (blockDim.x + 31) >> 5;
    v = (threadIdx.x < nw) ? sh[threadIdx.x] : 0.f;
    if (!w) {
        #pragma unroll
        for (int o = 16; o; o >>= 1) v += __shfl_down_sync(0xffffffffu, v, o);
    }
    __syncthreads();
    return v;
}

__device__ __forceinline__ float tf32r(float x) {
    asm("cvt.rna.tf32.f32 %0, %0;" : "+f"(x));
    return x;
}

__device__ __forceinline__ uint32_t smem_u32(const void* p) {
    uint32_t a;
    asm("{ .reg .u64 t; cvta.to.shared.u64 t, %1; cvt.u32.u64 %0, t; }"
        : "=r"(a) : "l"(p));
    return a;
}

__device__ __forceinline__ void cp16(uint32_t dst, const float* src) {
    asm volatile("cp.async.cg.shared.global [%0], [%1], 16;\n" :: "r"(dst), "l"(src));
}

__device__ __forceinline__ void ldsm4(uint32_t* r, uint32_t addr) {
    asm volatile("ldmatrix.sync.aligned.m8n8.x4.shared.b16 {%0,%1,%2,%3}, [%4];\n"
                 : "=r"(r[0]), "=r"(r[1]), "=r"(r[2]), "=r"(r[3]) : "r"(addr));
}

__device__ __forceinline__ void mma_tf32(float* c, const uint32_t* a, const uint32_t* b) {
    asm volatile(
        "mma.sync.aligned.m16n8k8.row.col.f32.tf32.tf32.f32 "
        "{%0,%1,%2,%3}, {%4,%5,%6,%7}, {%8,%9}, {%0,%1,%2,%3};\n"
        : "+f"(c[0]), "+f"(c[1]), "+f"(c[2]), "+f"(c[3])
        : "r"(a[0]), "r"(a[1]), "r"(a[2]), "r"(a[3]), "r"(b[0]), "r"(b[1]));
}

__device__ __forceinline__ void mma_bf16(float* c, const uint32_t* a, const uint32_t* b) {
    asm volatile(
        "mma.sync.aligned.m16n8k16.row.col.f32.bf16.bf16.f32 "
        "{%0,%1,%2,%3}, {%4,%5,%6,%7}, {%8,%9}, {%0,%1,%2,%3};\n"
        : "+f"(c[0]), "+f"(c[1]), "+f"(c[2]), "+f"(c[3])
        : "r"(a[0]), "r"(a[1]), "r"(a[2]), "r"(a[3]), "r"(b[0]), "r"(b[1]));
}

__device__ __forceinline__ uint32_t bf2(float hi, float lo) {
    uint32_t r;
    asm("cvt.rn.bf16x2.f32 %0, %1, %2;" : "=r"(r) : "f"(hi), "f"(lo));
    return r;
}

__device__ __forceinline__ void sts128(uint32_t addr, uint32_t w0, uint32_t w1,
                                       uint32_t w2, uint32_t w3) {
    asm volatile("st.shared.v4.b32 [%0], {%1,%2,%3,%4};"
                 :: "r"(addr), "r"(w0), "r"(w1), "r"(w2), "r"(w3));
}

// ---------------- 1. normalize rows + fn2 + negmask init ----------------
__global__ void prep_kernel(const float* __restrict__ feat,
                            const float* __restrict__ text) {
    int mi = blockIdx.x * 128 + threadIdx.x;
    if (mi < NN) g_negmask[mi] = 1;

    int pb = blockIdx.x;
    int p = pb / BB, b = pb % BB;
    const float* f = feat + (size_t)pb * DD;
    const float* t = text + ((size_t)b * PP + p) * DD;
    float s1 = 0.f, s2 = 0.f;
    for (int d = threadIdx.x; d < DD; d += 128) {
        float v = f[d]; s1 += v * v;
        float w = t[d]; s2 += w * w;
    }
    __shared__ float inv1, inv2;
    float r1 = blockReduceSum(s1);
    if (threadIdx.x == 0) {
        g_fn2[pb] = r1;
        inv1 = 1.f / fmaxf(sqrtf(r1), 1e-12f);
    }
    float r2 = blockReduceSum(s2);
    if (threadIdx.x == 0) inv2 = 1.f / fmaxf(sqrtf(r2), 1e-12f);
    __syncthreads();
    for (int d = threadIdx.x; d < DD; d += 128) {
        g_img[(size_t)pb * DD + d] = tf32r(f[d] * inv1);
        g_txt[(size_t)pb * DD + d] = tf32r(t[d] * inv2);
    }
}

// ---------------- 2. neg mask scatter ----------------
__global__ void mask_scatter_kernel(const int* __restrict__ ci,
                                    const int* __restrict__ pos) {
    int i = blockIdx.x * 256 + threadIdx.x;
    if (i < BB * KK)            g_negmask[ci[i]] = 0;
    else if (i < BB * KK + BB)  g_negmask[pos[i - BB * KK]] = 0;
}

// ---------------- 3. NEG GEMM: bf16 m16n8k16 legacy mma ----------------
// grid (NTILES, P), 256 threads. Stages f32 via LDG -> cvt.bf16x2 -> STS,
// register double-buffer, 2 smem stages, 1 sync/chunk. cn2 exact from the
// f32 staging registers. Epilogue = masked exp-dist row sums.
__global__ __launch_bounds__(256) void neg_bf16_kernel(
        const float* __restrict__ feat, const float* __restrict__ centers) {
    __shared__ __align__(16) uint16_t Asm[2][BB*SRS];
    __shared__ __align__(16) uint16_t Bsm[2][BB*SRS];
    __shared__ float redp[4][BB];
    __shared__ float cn2s[BB];

    int p = blockIdx.y, n0 = blockIdx.x * NT;
    const float* Ap = feat + (size_t)p * BB * DD;
    const float* Bp = centers + ((size_t)p * NN + n0) * DD;

    int t = threadIdx.x, lane = t & 31, wid = t >> 5;
    int g = lane >> 2, tig = lane & 3;
    int warpM = (wid >> 2) * 64;
    int warpN = (wid & 3) * 32;
    int q = lane >> 3, r = lane & 7;

    uint32_t sA = smem_u32(Asm), sB = smem_u32(Bsm);
    // ldmatrix base addresses (bytes), relative to stage base
    uint32_t aRM = sA + (warpM + (q & 1) * 8 + r) * (SRS * 2) + (q >> 1) * 16;
    uint32_t bRM = sB + (warpN + (q >> 1) * 8 + r) * (SRS * 2) + (q & 1) * 16;

    // staging: row = t>>1, half = t&1 covers f32 cols half*16..+15 of chunk
    int srow = t >> 1, half = t & 1;
    const float4* gA = (const float4*)(Ap + (size_t)srow * DD + half * 16);
    const float4* gB = (const float4*)(Bp + (size_t)srow * DD + half * 16);
    uint32_t stA = sA + srow * (SRS * 2) + half * 32;
    uint32_t stB = sB + srow * (SRS * 2) + half * 32;

    float acc[4][4][4];
    #pragma unroll
    for (int i = 0; i < 4; i++)
        #pragma unroll
        for (int j = 0; j < 4; j++)
            #pragma unroll
            for (int z = 0; z < 4; z++) acc[i][j][z] = 0.f;

    float csq = 0.f;
    float4 ra[4], rb[4];

    // prologue: load chunk 0 (each chunk advances 32 floats = 8 float4)
    #pragma unroll
    for (int i = 0; i < 4; i++) { ra[i] = gA[i]; rb[i] = gB[i]; }

    for (int c = 0; c < NCH; c++) {
        int buf = c & 1;
        uint32_t dA = stA + buf * TILEB;
        uint32_t dB = stB + buf * TILEB;
        // convert + store chunk c
        sts128(dA, bf2(ra[0].y, ra[0].x), bf2(ra[0].w, ra[0].z),
                   bf2(ra[1].y, ra[1].x), bf2(ra[1].w, ra[1].z));
        sts128(dA + 16, bf2(ra[2].y, ra[2].x), bf2(ra[2].w, ra[2].z),
                        bf2(ra[3].y, ra[3].x), bf2(ra[3].w, ra[3].z));
        sts128(dB, bf2(rb[0].y, rb[0].x), bf2(rb[0].w, rb[0].z),
                   bf2(rb[1].y, rb[1].x), bf2(rb[1].w, rb[1].z));
        sts128(dB + 16, bf2(rb[2].y, rb[2].x), bf2(rb[2].w, rb[2].z),
                        bf2(rb[3].y, rb[3].x), bf2(rb[3].w, rb[3].z));
        // exact cn2 from f32 regs (before overwrite)
        #pragma unroll
        for (int i = 0; i < 4; i++)
            csq += rb[i].x*rb[i].x + rb[i].y*rb[i].y + rb[i].z*rb[i].z + rb[i].w*rb[i].w;
        __syncthreads();

        if (c + 1 < NCH) {   // prefetch chunk c+1 (consumed next iter top)
            const float4* gA2 = gA + (c + 1) * 8;
            const float4* gB2 = gB + (c + 1) * 8;
            #pragma unroll
            for (int i = 0; i < 4; i++) { ra[i] = gA2[i]; rb[i] = gB2[i]; }
        }

        // compute: 2 x k16 steps on buf
        uint32_t soff = buf * TILEB;
        #pragma unroll
        for (int ks = 0; ks < 2; ks++) {
            uint32_t koff = soff + ks * 32;
            uint32_t af[4][4], bf[4][2];
            #pragma unroll
            for (int mt = 0; mt < 4; mt++)
                ldsm4(af[mt], aRM + koff + mt * (16 * SRS * 2));
            {
                uint32_t tmp[4];
                ldsm4(tmp, bRM + koff);
                bf[0][0]=tmp[0]; bf[0][1]=tmp[1]; bf[1][0]=tmp[2]; bf[1][1]=tmp[3];
                ldsm4(tmp, bRM + koff + 16 * SRS * 2);
                bf[2][0]=tmp[0]; bf[2][1]=tmp[1]; bf[3][0]=tmp[2]; bf[3][1]=tmp[3];
            }
            #pragma unroll
            for (int mt = 0; mt < 4; mt++)
                #pragma unroll
                for (int nt = 0; nt < 4; nt++)
                    mma_bf16(acc[mt][nt], af[mt], bf[nt]);
        }
        // next iteration's STS targets the other buffer; the sync above
        // transitively orders compute(buf) before any later STS to buf.
    }
    __syncthreads();

    // finalize cn2 (threads t, t^1 share row srow)
    csq += __shfl_xor_sync(0xffffffffu, csq, 1);
    if (half == 0) cn2s[srow] = csq;
    __syncthreads();

    float rsum[4][2];
    #pragma unroll
    for (int mt = 0; mt < 4; mt++) { rsum[mt][0] = 0.f; rsum[mt][1] = 0.f; }

    float f0[4], f1[4];
    #pragma unroll
    for (int mt = 0; mt < 4; mt++) {
        f0[mt] = g_fn2[p * BB + warpM + mt * 16 + g];
        f1[mt] = g_fn2[p * BB + warpM + mt * 16 + g + 8];
    }
    #pragma unroll
    for (int nt = 0; nt < 4; nt++) {
        int c0 = warpN + nt * 8 + 2 * tig;
        int c1 = c0 + 1;
        bool m0 = g_negmask[n0 + c0] != 0;
        bool m1 = g_negmask[n0 + c1] != 0;
        float cn0 = cn2s[c0], cn1 = cn2s[c1];
        #pragma unroll
        for (int mt = 0; mt < 4; mt++) {
            if (m0) {
                float pd2 = f0[mt] + cn0 - 2.f * acc[mt][nt][0];
                rsum[mt][0] += __expf(-SCALE_C * sqrtf(fmaxf(pd2, 1e-12f)));
                pd2 = f1[mt] + cn0 - 2.f * acc[mt][nt][2];
                rsum[mt][1] += __expf(-SCALE_C * sqrtf(fmaxf(pd2, 1e-12f)));
            }
            if (m1) {
                float pd2 = f0[mt] + cn1 - 2.f * acc[mt][nt][1];
                rsum[mt][0] += __expf(-SCALE_C * sqrtf(fmaxf(pd2, 1e-12f)));
                pd2 = f1[mt] + cn1 - 2.f * acc[mt][nt][3];
                rsum[mt][1] += __expf(-SCALE_C * sqrtf(fmaxf(pd2, 1e-12f)));
            }
        }
    }
    #pragma unroll
    for (int mt = 0; mt < 4; mt++) {
        #pragma unroll
        for (int h = 0; h < 2; h++) {
            float v = rsum[mt][h];
            v += __shfl_xor_sync(0xffffffffu, v, 1);
            v += __shfl_xor_sync(0xffffffffu, v, 2);
            rsum[mt][h] = v;
        }
    }
    if (tig == 0) {
        #pragma unroll
        for (int mt = 0; mt < 4; mt++) {
            redp[wid & 3][warpM + mt * 16 + g]     = rsum[mt][0];
            redp[wid & 3][warpM + mt * 16 + g + 8] = rsum[mt][1];
        }
    }
    __syncthreads();
    if (t < BB) {
        float s = redp[0][t] + redp[1][t] + redp[2][t] + redp[3][t];
        g_partial[((size_t)p * NTILES + blockIdx.x) * BB + t] = s;
    }
}

// ---------------- 3s. sim GEMM (tf32 legacy path, K-split x4) ----------------
__global__ __launch_bounds__(256) void sim_gemm_kernel() {
    extern __shared__ __align__(16) float dyn[];
    float* AsBase = dyn;
    float* BsBase = dyn + NSTG * STAGE_F;

    int p = blockIdx.y;
    const int NC = 8;
    int sel = blockIdx.x >> 2, kz = blockIdx.x & 3;
    const float* src = (sel ? g_txt : g_img) + (size_t)p * BB * DD + kz * 128;
    const float* Aptr = src;
    const float* Bptr = src;
    float* partdst = g_simpart + (size_t)((sel * PP + p) * 4 + kz) * BB * BB;

    int t = threadIdx.x;
    int lane = t & 31, wid = t >> 5;
    int g = lane >> 2, tig = lane & 3;
    int warpM = (wid >> 2) * 64;
    int warpN = (wid & 3) * 32;
    int q = lane >> 3, r = lane & 7;

    uint32_t sA = smem_u32(AsBase), sB = smem_u32(BsBase);
    uint32_t aRM = sA + (((warpM + (q & 1) * 8 + r) * RS + (q >> 1) * 4) << 2);
    uint32_t bRM = sB + (((warpN + (q >> 1) * 8 + r) * RS + (q & 1) * 4) << 2);

    int srow = t >> 1, kh = t & 1;
    uint32_t dA = sA + ((srow * RS + kh * 8) << 2);
    uint32_t dB = sB + ((srow * RS + kh * 8) << 2);
    const float* gA = Aptr + (size_t)srow * DD + kh * 8;
    const float* gB = Bptr + (size_t)srow * DD + kh * 8;

    float acc[4][4][4];
    #pragma unroll
    for (int i = 0; i < 4; i++)
        #pragma unroll
        for (int j = 0; j < 4; j++)
            #pragma unroll
            for (int z = 0; z < 4; z++) acc[i][j][z] = 0.f;

    #pragma unroll
    for (int s = 0; s < NSTG - 1; s++) {
        uint32_t off = (uint32_t)(s * STAGE_F) << 2;
        const float* gA2 = gA + s * 16;
        const float* gB2 = gB + s * 16;
        cp16(dA + off, gA2); cp16(dA + off + 16, gA2 + 4);
        cp16(dB + off, gB2); cp16(dB + off + 16, gB2 + 4);
        asm volatile("cp.async.commit_group;\n");
    }

    for (int c = 0; c < NC; c++) {
        asm volatile("cp.async.wait_group 2;\n");
        __syncthreads();

        if (c + NSTG - 1 < NC) {
            int s = c + NSTG - 1;
            uint32_t off = (uint32_t)((s & (NSTG - 1)) * STAGE_F) << 2;
            const float* gA2 = gA + s * 16;
            const float* gB2 = gB + s * 16;
            cp16(dA + off, gA2); cp16(dA + off + 16, gA2 + 4);
            cp16(dB + off, gB2); cp16(dB + off + 16, gB2 + 4);
        }
        asm volatile("cp.async.commit_group;\n");

        int buf = c & (NSTG - 1);
        uint32_t soff = (uint32_t)(buf * STAGE_F) << 2;
        #pragma unroll
        for (int ks = 0; ks < 2; ks++) {
            uint32_t koff = soff + ks * 32;
            uint32_t af[4][4], bf[4][2];
            #pragma unroll
            for (int mt = 0; mt < 4; mt++)
                ldsm4(af[mt], aRM + koff + mt * (16 * RS * 4));
            {
                uint32_t tmp[4];
                ldsm4(tmp, bRM + koff);
                bf[0][0]=tmp[0]; bf[0][1]=tmp[1]; bf[1][0]=tmp[2]; bf[1][1]=tmp[3];
                ldsm4(tmp, bRM + koff + 16 * RS * 4);
                bf[2][0]=tmp[0]; bf[2][1]=tmp[1]; bf[3][0]=tmp[2]; bf[3][1]=tmp[3];
            }
            #pragma unroll
            for (int mt = 0; mt < 4; mt++)
                #pragma unroll
                for (int nt = 0; nt < 4; nt++)
                    mma_tf32(acc[mt][nt], af[mt], bf[nt]);
        }
    }
    __syncthreads();

    #pragma unroll
    for (int mt = 0; mt < 4; mt++) {
        int r0 = warpM + mt * 16 + g;
        int r1 = r0 + 8;
        #pragma unroll
        for (int nt = 0; nt < 4; nt++) {
            int c0 = warpN + nt * 8 + 2 * tig;
            partdst[r0 * BB + c0]     = acc[mt][nt][0];
            partdst[r0 * BB + c0 + 1] = acc[mt][nt][1];
            partdst[r1 * BB + c0]     = acc[mt][nt][2];
            partdst[r1 * BB + c0 + 1] = acc[mt][nt][3];
        }
    }
}

// ---------------- 3b. combine sim K-split partials ----------------
__global__ void sim_combine_kernel() {
    int sp = blockIdx.x;
    int sel = sp >> 2, p = sp & 3;
    const float4* b0 = (const float4*)(g_simpart + (size_t)sp * 4 * BB * BB);
    const float4* b1 = b0 + (BB * BB / 4);
    const float4* b2 = b1 + (BB * BB / 4);
    const float4* b3 = b2 + (BB * BB / 4);
    float4* dst = (float4*)((sel ? g_txtsim : g_imgsim) + (size_t)p * BB * BB);
    for (int i = threadIdx.x; i < BB * BB / 4; i += 256) {
        float4 a = b0[i], b = b1[i], c = b2[i], d = b3[i];
        float4 o;
        o.x = (a.x + b.x + c.x + d.x) * INV_TEMP;
        o.y = (a.y + b.y + c.y + d.y) * INV_TEMP;
        o.z = (a.z + b.z + c.z + d.z) * INV_TEMP;
        o.w = (a.w + b.w + c.w + d.w) * INV_TEMP;
        dst[i] = o;
    }
}

// ---------------- 4. fused neg-reduce + positive distances ----------------
__global__ void reduce_pos_kernel(const float* __restrict__ feat,
                                  const float* __restrict__ centers,
                                  const int* __restrict__ ci) {
    int pb = blockIdx.x;
    int p = pb / BB, b = pb % BB;
    int t = threadIdx.x, lane = t & 31, wid = t >> 5;

    float s = g_partial[((size_t)p * NTILES + t) * BB + b]
            + g_partial[((size_t)p * NTILES + t + 128) * BB + b];
    float rneg = blockReduceSum(s);
    if (t == 0) g_negsum[pb] = rneg;

    __shared__ float wsum[4];
    const float4* f = (const float4*)(feat + (size_t)pb * DD);
    float fn2v = g_fn2[pb];
    float part = 0.f;
    for (int k = wid; k < KK; k += 4) {
        int idx = ci[b * KK + k];
        const float4* c = (const float4*)(centers + ((size_t)p * NN + idx) * DD);
        float dot = 0.f, pn2 = 0.f;
        #pragma unroll
        for (int qq = lane; qq < DD / 4; qq += 32) {
            float4 a = f[qq], bv = c[qq];
            dot += a.x * bv.x + a.y * bv.y + a.z * bv.z + a.w * bv.w;
            pn2 += bv.x * bv.x + bv.y * bv.y + bv.z * bv.z + bv.w * bv.w;
        }
        #pragma unroll
        for (int o = 16; o; o >>= 1) {
            dot += __shfl_down_sync(0xffffffffu, dot, o);
            pn2 += __shfl_down_sync(0xffffffffu, pn2, o);
        }
        if (lane == 0) {
            float pd2 = fn2v + pn2 - 2.f * dot;
            part += expf(-SCALE_C * sqrtf(fmaxf(pd2, 1e-12f)));
        }
    }
    if (lane == 0) wsum[wid] = part;
    __syncthreads();
    if (t == 0) g_possum[pb] = wsum[0] + wsum[1] + wsum[2] + wsum[3];
}

// ---------------- 5. align / KL loss ----------------
__global__ void align_kernel() {
    int p = blockIdx.x;
    int b = threadIdx.x;
    const float* imrow = g_imgsim + ((size_t)p * BB + b) * BB;
    const float* txrow = g_txtsim + ((size_t)p * BB + b) * BB;
    __shared__ unsigned char shv[BB];
    bool v = false;
    for (int c = 0; c < BB; c++)
        if (imrow[c] > SIM_THR && txrow[c] > SIM_THR) v = true;
    shv[b] = v ? 1 : 0;
    __syncthreads();

    float mi = NEG_INF_F, mt = NEG_INF_F;
    for (int c = 0; c < BB; c++)
        if (shv[c]) { mi = fmaxf(mi, imrow[c]); mt = fmaxf(mt, txrow[c]); }
    float si = 0.f, st = 0.f;
    for (int c = 0; c < BB; c++)
        if (shv[c]) { si += expf(imrow[c] - mi); st += expf(txrow[c] - mt); }
    float lsei = logf(si) + mi;
    float lset = logf(st) + mt;
    float kl1 = 0.f, kl2 = 0.f;
    for (int c = 0; c < BB; c++) {
        if (shv[c]) {
            float ilp = imrow[c] - lsei;
            float tlp = txrow[c] - lset;
            kl1 += expf(tlp) * (tlp - ilp);
            kl2 += expf(ilp) * (ilp - tlp);
        }
    }
    float c1 = v ? kl1 : 0.f;
    float c2 = v ? kl2 : 0.f;
    float nvf = v ? 1.f : 0.f;
    float r1 = blockReduceSum(c1);
    __shared__ float sr1;
    if (b == 0) sr1 = r1;
    float r2 = blockReduceSum(c2);
    __shared__ float sr2;
    if (b == 0) sr2 = r2;
    float nv = blockReduceSum(nvf);
    if (b == 0) {
        int n = (int)(nv + 0.5f);
        float per = (n > 0) ? 0.5f * (sr1 + sr2) / (float)max(n, 1) : 0.f;
        g_alignpart[p] = per;
    }
}

// ---------------- 6. final combine + pos_vid gather ----------------
__global__ void final_kernel(const int* __restrict__ vid,
                             const int* __restrict__ ci,
                             float* __restrict__ out) {
    int b = threadIdx.x;
    for (int i = b; i < BB * KK; i += 128) out[3 + i] = (float)vid[ci[i]];

    __shared__ float sacc;
    if (b == 0) sacc = 0.f;
    __syncthreads();
    for (int p = 0; p < PP; p++) {
        float v = logf(g_negsum[p * BB + b]) - logf(g_possum[p * BB + b]);
        float r = blockReduceSum(v);
        if (b == 0) {
            float lp = r / (float)BB;
            if (isnan(lp)) lp = 0.f;
            sacc += lp;
        }
        __syncthreads();
    }
    if (b == 0) {
        float contrastive = sacc / (float)PP;
        float align = g_alignpart[0] + g_alignpart[1] + g_alignpart[2] + g_alignpart[3];
        out[0] = contrastive + KLW * align;
        out[1] = contrastive;
        out[2] = align;
    }
}

// ---------------- launch ----------------
extern "C" void kernel_launch(void* const* d_in, const int* in_sizes, int n_in,
                              void* d_out, int out_size) {
    const float* feature = (const float*)d_in[0];
    const float* text    = (const float*)d_in[1];
    const float* centers = (const float*)d_in[2];
    const int*   pos     = (const int*)d_in[3];
    const int*   ci      = (const int*)d_in[4];
    const int*   vid     = (const int*)d_in[5];
    float* out = (float*)d_out;

    cudaFuncSetAttribute(sim_gemm_kernel,
                         cudaFuncAttributeMaxDynamicSharedMemorySize, DSMEM_BYTES);

    prep_kernel<<<PP * BB, 128>>>(feature, text);
    mask_scatter_kernel<<<(BB * KK + BB + 255) / 256, 256>>>(ci, pos);
    neg_bf16_kernel<<<dim3(NTILES, PP), 256>>>(feature, centers);
    sim_gemm_kernel<<<dim3(8, PP), 256, DSMEM_BYTES>>>();
    sim_combine_kernel<<<2 * PP, 256>>>();
    reduce_pos_kernel<<<PP * BB, 128>>>(feature, centers, ci);
    align_kernel<<<PP, 128>>>();
    final_kernel<<<1, 128>>>(vid, ci, out);
}

// round 14
// speedup vs baseline: 3.5568x; 1.2751x over previous
#include <cuda_runtime.h>
#include <math.h>
#include <stdint.h>

#define PP 4
#define BB 128
#define DD 512
#define NN 32768
#define KK 10
#define NT 128
#define NTILES (NN/NT)   /* 256 */
#define SCALE_C 10.0f
#define INV_TEMP 2.0f
#define SIM_THR 0.7f
#define KLW 0.4916666666666667f
#define NEG_INF_F (-1e30f)

/* sim (tf32 legacy) geometry */
#define RS 20
#define STAGE_F (BB*RS)
#define NSTG 4
#define DSMEM_BYTES (2*NSTG*STAGE_F*4)   /* 81920 */

/* neg (bf16 legacy) geometry */
#define KCH 32                  /* K elements per chunk */
#define NCH (DD/KCH)            /* 16 chunks */
#define SRS 40                  /* smem row stride in bf16 (80 bytes) */
#define TILEB (BB*SRS*2)        /* 10240 bytes per matrix per stage */

// ---------------- device scratch ----------------
__device__ float g_img[PP*BB*DD];
__device__ float g_txt[PP*BB*DD];
__device__ float g_fn2[PP*BB];
__device__ float g_simpart[2*PP*4*BB*BB];
__device__ float g_imgsim[PP*BB*BB];
__device__ float g_txtsim[PP*BB*BB];
__device__ unsigned char g_negmask[NN];
__device__ float g_partial[PP*NTILES*BB];
__device__ float g_negsum[PP*BB];
__device__ float g_possum[PP*BB];
__device__ float g_valid[PP*BB];
__device__ float g_rowkl[PP*BB];

// ---------------- helpers ----------------
__device__ __forceinline__ float blockReduceSum(float v) {
    __shared__ float sh[32];
    int lane = threadIdx.x & 31, w = threadIdx.x >> 5;
    #pragma unroll
    for (int o = 16; o; o >>= 1) v += __shfl_down_sync(0xffffffffu, v, o);
    if (!lane) sh[w] = v;
    __syncthreads();
    int nw = (blockDim.x + 31) >> 5;
    v = (threadIdx.x < nw) ? sh[threadIdx.x] : 0.f;
    if (!w) {
        #pragma unroll
        for (int o = 16; o; o >>= 1) v += __shfl_down_sync(0xffffffffu, v, o);
    }
    __syncthreads();
    return v;  // valid on thread 0
}

__device__ __forceinline__ float blockReduceMax(float v) {
    __shared__ float shm[32];
    int lane = threadIdx.x & 31, w = threadIdx.x >> 5;
    #pragma unroll
    for (int o = 16; o; o >>= 1) v = fmaxf(v, __shfl_down_sync(0xffffffffu, v, o));
    if (!lane) shm[w] = v;
    __syncthreads();
    int nw = (blockDim.x + 31) >> 5;
    v = (threadIdx.x < nw) ? shm[threadIdx.x] : NEG_INF_F;
    if (!w) {
        #pragma unroll
        for (int o = 16; o; o >>= 1) v = fmaxf(v, __shfl_down_sync(0xffffffffu, v, o));
    }
    __syncthreads();
    return v;  // valid on thread 0
}

__device__ __forceinline__ float bcastSum(float v) {
    float r = blockReduceSum(v);
    __shared__ float s;
    if (threadIdx.x == 0) s = r;
    __syncthreads();
    return s;
}

__device__ __forceinline__ float bcastMax(float v) {
    float r = blockReduceMax(v);
    __shared__ float s;
    if (threadIdx.x == 0) s = r;
    __syncthreads();
    return s;
}

__device__ __forceinline__ float tf32r(float x) {
    asm("cvt.rna.tf32.f32 %0, %0;" : "+f"(x));
    return x;
}

__device__ __forceinline__ uint32_t smem_u32(const void* p) {
    uint32_t a;
    asm("{ .reg .u64 t; cvta.to.shared.u64 t, %1; cvt.u32.u64 %0, t; }"
        : "=r"(a) : "l"(p));
    return a;
}

__device__ __forceinline__ void cp16(uint32_t dst, const float* src) {
    asm volatile("cp.async.cg.shared.global [%0], [%1], 16;\n" :: "r"(dst), "l"(src));
}

__device__ __forceinline__ void ldsm4(uint32_t* r, uint32_t addr) {
    asm volatile("ldmatrix.sync.aligned.m8n8.x4.shared.b16 {%0,%1,%2,%3}, [%4];\n"
                 : "=r"(r[0]), "=r"(r[1]), "=r"(r[2]), "=r"(r[3]) : "r"(addr));
}

__device__ __forceinline__ void mma_tf32(float* c, const uint32_t* a, const uint32_t* b) {
    asm volatile(
        "mma.sync.aligned.m16n8k8.row.col.f32.tf32.tf32.f32 "
        "{%0,%1,%2,%3}, {%4,%5,%6,%7}, {%8,%9}, {%0,%1,%2,%3};\n"
        : "+f"(c[0]), "+f"(c[1]), "+f"(c[2]), "+f"(c[3])
        : "r"(a[0]), "r"(a[1]), "r"(a[2]), "r"(a[3]), "r"(b[0]), "r"(b[1]));
}

__device__ __forceinline__ void mma_bf16(float* c, const uint32_t* a, const uint32_t* b) {
    asm volatile(
        "mma.sync.aligned.m16n8k16.row.col.f32.bf16.bf16.f32 "
        "{%0,%1,%2,%3}, {%4,%5,%6,%7}, {%8,%9}, {%0,%1,%2,%3};\n"
        : "+f"(c[0]), "+f"(c[1]), "+f"(c[2]), "+f"(c[3])
        : "r"(a[0]), "r"(a[1]), "r"(a[2]), "r"(a[3]), "r"(b[0]), "r"(b[1]));
}

__device__ __forceinline__ uint32_t bf2(float hi, float lo) {
    uint32_t r;
    asm("cvt.rn.bf16x2.f32 %0, %1, %2;" : "=r"(r) : "f"(hi), "f"(lo));
    return r;
}

__device__ __forceinline__ void sts128(uint32_t addr, uint32_t w0, uint32_t w1,
                                       uint32_t w2, uint32_t w3) {
    asm volatile("st.shared.v4.b32 [%0], {%1,%2,%3,%4};"
                 :: "r"(addr), "r"(w0), "r"(w1), "r"(w2), "r"(w3));
}

// ---------------- 1. normalize rows + fn2 + negmask init ----------------
__global__ void prep_kernel(const float* __restrict__ feat,
                            const float* __restrict__ text) {
    int mi = blockIdx.x * 128 + threadIdx.x;
    if (mi < NN) g_negmask[mi] = 1;

    int pb = blockIdx.x;
    int p = pb / BB, b = pb % BB;
    const float* f = feat + (size_t)pb * DD;
    const float* t = text + ((size_t)b * PP + p) * DD;
    float s1 = 0.f, s2 = 0.f;
    for (int d = threadIdx.x; d < DD; d += 128) {
        float v = f[d]; s1 += v * v;
        float w = t[d]; s2 += w * w;
    }
    __shared__ float inv1, inv2;
    float r1 = blockReduceSum(s1);
    if (threadIdx.x == 0) {
        g_fn2[pb] = r1;
        inv1 = 1.f / fmaxf(sqrtf(r1), 1e-12f);
    }
    float r2 = blockReduceSum(s2);
    if (threadIdx.x == 0) inv2 = 1.f / fmaxf(sqrtf(r2), 1e-12f);
    __syncthreads();
    for (int d = threadIdx.x; d < DD; d += 128) {
        g_img[(size_t)pb * DD + d] = tf32r(f[d] * inv1);
        g_txt[(size_t)pb * DD + d] = tf32r(t[d] * inv2);
    }
}

// ---------------- 2. neg mask scatter ----------------
__global__ void mask_scatter_kernel(const int* __restrict__ ci,
                                    const int* __restrict__ pos) {
    int i = blockIdx.x * 256 + threadIdx.x;
    if (i < BB * KK)            g_negmask[ci[i]] = 0;
    else if (i < BB * KK + BB)  g_negmask[pos[i - BB * KK]] = 0;
}

// ---------------- 3. NEG GEMM: bf16 m16n8k16 legacy mma ----------------
__global__ __launch_bounds__(256, 2) void neg_bf16_kernel(
        const float* __restrict__ feat, const float* __restrict__ centers) {
    __shared__ __align__(16) uint16_t Asm[2][BB*SRS];
    __shared__ __align__(16) uint16_t Bsm[2][BB*SRS];
    __shared__ float redp[4][BB];
    __shared__ float cn2s[BB];

    int p = blockIdx.y, n0 = blockIdx.x * NT;
    const float* Ap = feat + (size_t)p * BB * DD;
    const float* Bp = centers + ((size_t)p * NN + n0) * DD;

    int t = threadIdx.x, lane = t & 31, wid = t >> 5;
    int g = lane >> 2, tig = lane & 3;
    int warpM = (wid >> 2) * 64;
    int warpN = (wid & 3) * 32;
    int q = lane >> 3, r = lane & 7;

    uint32_t sA = smem_u32(Asm), sB = smem_u32(Bsm);
    uint32_t aRM = sA + (warpM + (q & 1) * 8 + r) * (SRS * 2) + (q >> 1) * 16;
    uint32_t bRM = sB + (warpN + (q >> 1) * 8 + r) * (SRS * 2) + (q & 1) * 16;

    int srow = t >> 1, half = t & 1;
    const float4* gA = (const float4*)(Ap + (size_t)srow * DD + half * 16);
    const float4* gB = (const float4*)(Bp + (size_t)srow * DD + half * 16);
    uint32_t stA = sA + srow * (SRS * 2) + half * 32;
    uint32_t stB = sB + srow * (SRS * 2) + half * 32;

    float acc[4][4][4];
    #pragma unroll
    for (int i = 0; i < 4; i++)
        #pragma unroll
        for (int j = 0; j < 4; j++)
            #pragma unroll
            for (int z = 0; z < 4; z++) acc[i][j][z] = 0.f;

    float csq = 0.f;
    float4 ra[4], rb[4];

    #pragma unroll
    for (int i = 0; i < 4; i++) { ra[i] = gA[i]; rb[i] = gB[i]; }

    for (int c = 0; c < NCH; c++) {
        int buf = c & 1;
        uint32_t dA = stA + buf * TILEB;
        uint32_t dB = stB + buf * TILEB;
        sts128(dA, bf2(ra[0].y, ra[0].x), bf2(ra[0].w, ra[0].z),
                   bf2(ra[1].y, ra[1].x), bf2(ra[1].w, ra[1].z));
        sts128(dA + 16, bf2(ra[2].y, ra[2].x), bf2(ra[2].w, ra[2].z),
                        bf2(ra[3].y, ra[3].x), bf2(ra[3].w, ra[3].z));
        sts128(dB, bf2(rb[0].y, rb[0].x), bf2(rb[0].w, rb[0].z),
                   bf2(rb[1].y, rb[1].x), bf2(rb[1].w, rb[1].z));
        sts128(dB + 16, bf2(rb[2].y, rb[2].x), bf2(rb[2].w, rb[2].z),
                        bf2(rb[3].y, rb[3].x), bf2(rb[3].w, rb[3].z));
        #pragma unroll
        for (int i = 0; i < 4; i++)
            csq += rb[i].x*rb[i].x + rb[i].y*rb[i].y + rb[i].z*rb[i].z + rb[i].w*rb[i].w;
        __syncthreads();

        if (c + 1 < NCH) {
            const float4* gA2 = gA + (c + 1) * 8;
            const float4* gB2 = gB + (c + 1) * 8;
            #pragma unroll
            for (int i = 0; i < 4; i++) { ra[i] = gA2[i]; rb[i] = gB2[i]; }
        }

        uint32_t soff = buf * TILEB;
        #pragma unroll
        for (int ks = 0; ks < 2; ks++) {
            uint32_t koff = soff + ks * 32;
            uint32_t af[4][4], bf[4][2];
            #pragma unroll
            for (int mt = 0; mt < 4; mt++)
                ldsm4(af[mt], aRM + koff + mt * (16 * SRS * 2));
            {
                uint32_t tmp[4];
                ldsm4(tmp, bRM + koff);
                bf[0][0]=tmp[0]; bf[0][1]=tmp[1]; bf[1][0]=tmp[2]; bf[1][1]=tmp[3];
                ldsm4(tmp, bRM + koff + 16 * SRS * 2);
                bf[2][0]=tmp[0]; bf[2][1]=tmp[1]; bf[3][0]=tmp[2]; bf[3][1]=tmp[3];
            }
            #pragma unroll
            for (int mt = 0; mt < 4; mt++)
                #pragma unroll
                for (int nt = 0; nt < 4; nt++)
                    mma_bf16(acc[mt][nt], af[mt], bf[nt]);
        }
    }
    __syncthreads();

    csq += __shfl_xor_sync(0xffffffffu, csq, 1);
    if (half == 0) cn2s[srow] = csq;
    __syncthreads();

    float rsum[4][2];
    #pragma unroll
    for (int mt = 0; mt < 4; mt++) { rsum[mt][0] = 0.f; rsum[mt][1] = 0.f; }

    float f0[4], f1[4];
    #pragma unroll
    for (int mt = 0; mt < 4; mt++) {
        f0[mt] = g_fn2[p * BB + warpM + mt * 16 + g];
        f1[mt] = g_fn2[p * BB + warpM + mt * 16 + g + 8];
    }
    #pragma unroll
    for (int nt = 0; nt < 4; nt++) {
        int c0 = warpN + nt * 8 + 2 * tig;
        int c1 = c0 + 1;
        bool m0 = g_negmask[n0 + c0] != 0;
        bool m1 = g_negmask[n0 + c1] != 0;
        float cn0 = cn2s[c0], cn1 = cn2s[c1];
        #pragma unroll
        for (int mt = 0; mt < 4; mt++) {
            if (m0) {
                float pd2 = f0[mt] + cn0 - 2.f * acc[mt][nt][0];
                rsum[mt][0] += __expf(-SCALE_C * sqrtf(fmaxf(pd2, 1e-12f)));
                pd2 = f1[mt] + cn0 - 2.f * acc[mt][nt][2];
                rsum[mt][1] += __expf(-SCALE_C * sqrtf(fmaxf(pd2, 1e-12f)));
            }
            if (m1) {
                float pd2 = f0[mt] + cn1 - 2.f * acc[mt][nt][1];
                rsum[mt][0] += __expf(-SCALE_C * sqrtf(fmaxf(pd2, 1e-12f)));
                pd2 = f1[mt] + cn1 - 2.f * acc[mt][nt][3];
                rsum[mt][1] += __expf(-SCALE_C * sqrtf(fmaxf(pd2, 1e-12f)));
            }
        }
    }
    #pragma unroll
    for (int mt = 0; mt < 4; mt++) {
        #pragma unroll
        for (int h = 0; h < 2; h++) {
            float v = rsum[mt][h];
            v += __shfl_xor_sync(0xffffffffu, v, 1);
            v += __shfl_xor_sync(0xffffffffu, v, 2);
            rsum[mt][h] = v;
        }
    }
    if (tig == 0) {
        #pragma unroll
        for (int mt = 0; mt < 4; mt++) {
            redp[wid & 3][warpM + mt * 16 + g]     = rsum[mt][0];
            redp[wid & 3][warpM + mt * 16 + g + 8] = rsum[mt][1];
        }
    }
    __syncthreads();
    if (t < BB) {
        float s = redp[0][t] + redp[1][t] + redp[2][t] + redp[3][t];
        g_partial[((size_t)p * NTILES + blockIdx.x) * BB + t] = s;
    }
}

// ---------------- 3s. sim GEMM (tf32 legacy path, K-split x4) ----------------
__global__ __launch_bounds__(256) void sim_gemm_kernel() {
    extern __shared__ __align__(16) float dyn[];
    float* AsBase = dyn;
    float* BsBase = dyn + NSTG * STAGE_F;

    int p = blockIdx.y;
    const int NC = 8;
    int sel = blockIdx.x >> 2, kz = blockIdx.x & 3;
    const float* src = (sel ? g_txt : g_img) + (size_t)p * BB * DD + kz * 128;
    const float* Aptr = src;
    const float* Bptr = src;
    float* partdst = g_simpart + (size_t)((sel * PP + p) * 4 + kz) * BB * BB;

    int t = threadIdx.x;
    int lane = t & 31, wid = t >> 5;
    int g = lane >> 2, tig = lane & 3;
    int warpM = (wid >> 2) * 64;
    int warpN = (wid & 3) * 32;
    int q = lane >> 3, r = lane & 7;

    uint32_t sA = smem_u32(AsBase), sB = smem_u32(BsBase);
    uint32_t aRM = sA + (((warpM + (q & 1) * 8 + r) * RS + (q >> 1) * 4) << 2);
    uint32_t bRM = sB + (((warpN + (q >> 1) * 8 + r) * RS + (q & 1) * 4) << 2);

    int srow = t >> 1, kh = t & 1;
    uint32_t dA = sA + ((srow * RS + kh * 8) << 2);
    uint32_t dB = sB + ((srow * RS + kh * 8) << 2);
    const float* gA = Aptr + (size_t)srow * DD + kh * 8;
    const float* gB = Bptr + (size_t)srow * DD + kh * 8;

    float acc[4][4][4];
    #pragma unroll
    for (int i = 0; i < 4; i++)
        #pragma unroll
        for (int j = 0; j < 4; j++)
            #pragma unroll
            for (int z = 0; z < 4; z++) acc[i][j][z] = 0.f;

    #pragma unroll
    for (int s = 0; s < NSTG - 1; s++) {
        uint32_t off = (uint32_t)(s * STAGE_F) << 2;
        const float* gA2 = gA + s * 16;
        const float* gB2 = gB + s * 16;
        cp16(dA + off, gA2); cp16(dA + off + 16, gA2 + 4);
        cp16(dB + off, gB2); cp16(dB + off + 16, gB2 + 4);
        asm volatile("cp.async.commit_group;\n");
    }

    for (int c = 0; c < NC; c++) {
        asm volatile("cp.async.wait_group 2;\n");
        __syncthreads();

        if (c + NSTG - 1 < NC) {
            int s = c + NSTG - 1;
            uint32_t off = (uint32_t)((s & (NSTG - 1)) * STAGE_F) << 2;
            const float* gA2 = gA + s * 16;
            const float* gB2 = gB + s * 16;
            cp16(dA + off, gA2); cp16(dA + off + 16, gA2 + 4);
            cp16(dB + off, gB2); cp16(dB + off + 16, gB2 + 4);
        }
        asm volatile("cp.async.commit_group;\n");

        int buf = c & (NSTG - 1);
        uint32_t soff = (uint32_t)(buf * STAGE_F) << 2;
        #pragma unroll
        for (int ks = 0; ks < 2; ks++) {
            uint32_t koff = soff + ks * 32;
            uint32_t af[4][4], bf[4][2];
            #pragma unroll
            for (int mt = 0; mt < 4; mt++)
                ldsm4(af[mt], aRM + koff + mt * (16 * RS * 4));
            {
                uint32_t tmp[4];
                ldsm4(tmp, bRM + koff);
                bf[0][0]=tmp[0]; bf[0][1]=tmp[1]; bf[1][0]=tmp[2]; bf[1][1]=tmp[3];
                ldsm4(tmp, bRM + koff + 16 * RS * 4);
                bf[2][0]=tmp[0]; bf[2][1]=tmp[1]; bf[3][0]=tmp[2]; bf[3][1]=tmp[3];
            }
            #pragma unroll
            for (int mt = 0; mt < 4; mt++)
                #pragma unroll
                for (int nt = 0; nt < 4; nt++)
                    mma_tf32(acc[mt][nt], af[mt], bf[nt]);
        }
    }
    __syncthreads();

    #pragma unroll
    for (int mt = 0; mt < 4; mt++) {
        int r0 = warpM + mt * 16 + g;
        int r1 = r0 + 8;
        #pragma unroll
        for (int nt = 0; nt < 4; nt++) {
            int c0 = warpN + nt * 8 + 2 * tig;
            partdst[r0 * BB + c0]     = acc[mt][nt][0];
            partdst[r0 * BB + c0 + 1] = acc[mt][nt][1];
            partdst[r1 * BB + c0]     = acc[mt][nt][2];
            partdst[r1 * BB + c0 + 1] = acc[mt][nt][3];
        }
    }
}

// ---------------- 3b. combine sim K-split partials ----------------
__global__ void sim_combine_kernel() {
    int sp = blockIdx.x;
    int sel = sp >> 2, p = sp & 3;
    const float4* b0 = (const float4*)(g_simpart + (size_t)sp * 4 * BB * BB);
    const float4* b1 = b0 + (BB * BB / 4);
    const float4* b2 = b1 + (BB * BB / 4);
    const float4* b3 = b2 + (BB * BB / 4);
    float4* dst = (float4*)((sel ? g_txtsim : g_imgsim) + (size_t)p * BB * BB);
    for (int i = threadIdx.x; i < BB * BB / 4; i += 256) {
        float4 a = b0[i], b = b1[i], c = b2[i], d = b3[i];
        float4 o;
        o.x = (a.x + b.x + c.x + d.x) * INV_TEMP;
        o.y = (a.y + b.y + c.y + d.y) * INV_TEMP;
        o.z = (a.z + b.z + c.z + d.z) * INV_TEMP;
        o.w = (a.w + b.w + c.w + d.w) * INV_TEMP;
        dst[i] = o;
    }
}

// ---------------- 4a. per-row validity (row b valid if any col passes) -------
// grid PP*BB blocks of 128 threads (thread = column)
__global__ void valid_kernel() {
    int pb = blockIdx.x;
    int c = threadIdx.x;
    float im = g_imgsim[(size_t)pb * BB + c];
    float tx = g_txtsim[(size_t)pb * BB + c];
    int any = __syncthreads_or((im > SIM_THR && tx > SIM_THR) ? 1 : 0);
    if (c == 0) g_valid[pb] = any ? 1.f : 0.f;
}

// ---------------- 4b. align / KL per row (row-parallel) ----------------
// grid PP*BB blocks of 128 threads; thread c handles column c of row b
__global__ void align_kernel() {
    int pb = blockIdx.x;
    int p = pb / BB;
    int c = threadIdx.x;
    float im = g_imgsim[(size_t)pb * BB + c];
    float tx = g_txtsim[(size_t)pb * BB + c];
    bool vc = g_valid[p * BB + c] > 0.5f;

    float mi = bcastMax(vc ? im : NEG_INF_F);
    float mt = bcastMax(vc ? tx : NEG_INF_F);
    float si = bcastSum(vc ? expf(im - mi) : 0.f);
    float st = bcastSum(vc ? expf(tx - mt) : 0.f);
    float lsei = logf(si) + mi;
    float lset = logf(st) + mt;

    float kl = 0.f;
    if (vc) {
        float ilp = im - lsei;
        float tlp = tx - lset;
        kl = expf(tlp) * (tlp - ilp) + expf(ilp) * (ilp - tlp);
    }
    float ks = blockReduceSum(kl);
    if (c == 0) {
        bool vb = g_valid[pb] > 0.5f;
        g_rowkl[pb] = vb ? 0.5f * ks : 0.f;
    }
}

// ---------------- 5. fused neg-reduce + positive distances ----------------
__global__ void reduce_pos_kernel(const float* __restrict__ feat,
                                  const float* __restrict__ centers,
                                  const int* __restrict__ ci) {
    int pb = blockIdx.x;
    int p = pb / BB, b = pb % BB;
    int t = threadIdx.x, lane = t & 31, wid = t >> 5;

    float s = g_partial[((size_t)p * NTILES + t) * BB + b]
            + g_partial[((size_t)p * NTILES + t + 128) * BB + b];
    float rneg = blockReduceSum(s);
    if (t == 0) g_negsum[pb] = rneg;

    __shared__ float wsum[4];
    const float4* f = (const float4*)(feat + (size_t)pb * DD);
    float fn2v = g_fn2[pb];
    float part = 0.f;
    for (int k = wid; k < KK; k += 4) {
        int idx = ci[b * KK + k];
        const float4* c = (const float4*)(centers + ((size_t)p * NN + idx) * DD);
        float dot = 0.f, pn2 = 0.f;
        #pragma unroll
        for (int qq = lane; qq < DD / 4; qq += 32) {
            float4 a = f[qq], bv = c[qq];
            dot += a.x * bv.x + a.y * bv.y + a.z * bv.z + a.w * bv.w;
            pn2 += bv.x * bv.x + bv.y * bv.y + bv.z * bv.z + bv.w * bv.w;
        }
        #pragma unroll
        for (int o = 16; o; o >>= 1) {
            dot += __shfl_down_sync(0xffffffffu, dot, o);
            pn2 += __shfl_down_sync(0xffffffffu, pn2, o);
        }
        if (lane == 0) {
            float pd2 = fn2v + pn2 - 2.f * dot;
            part += expf(-SCALE_C * sqrtf(fmaxf(pd2, 1e-12f)));
        }
    }
    if (lane == 0) wsum[wid] = part;
    __syncthreads();
    if (t == 0) g_possum[pb] = wsum[0] + wsum[1] + wsum[2] + wsum[3];
}

// ---------------- 6. final combine + pos_vid gather ----------------
__global__ void final_kernel(const int* __restrict__ vid,
                             const int* __restrict__ ci,
                             float* __restrict__ out) {
    int b = threadIdx.x;
    for (int i = b; i < BB * KK; i += 128) out[3 + i] = (float)vid[ci[i]];

    __shared__ float sacc, salign;
    if (b == 0) { sacc = 0.f; salign = 0.f; }
    __syncthreads();
    for (int p = 0; p < PP; p++) {
        float v = logf(g_negsum[p * BB + b]) - logf(g_possum[p * BB + b]);
        float r = blockReduceSum(v);
        if (b == 0) {
            float lp = r / (float)BB;
            if (isnan(lp)) lp = 0.f;
            sacc += lp;
        }
        float rk = blockReduceSum(g_rowkl[p * BB + b]);
        float nv = blockReduceSum(g_valid[p * BB + b]);
        if (b == 0) {
            int n = (int)(nv + 0.5f);
            salign += (n > 0) ? rk / (float)n : 0.f;
        }
        __syncthreads();
    }
    if (b == 0) {
        float contrastive = sacc / (float)PP;
        float align = salign;
        out[0] = contrastive + KLW * align;
        out[1] = contrastive;
        out[2] = align;
    }
}

// ---------------- launch ----------------
extern "C" void kernel_launch(void* const* d_in, const int* in_sizes, int n_in,
                              void* d_out, int out_size) {
    const float* feature = (const float*)d_in[0];
    const float* text    = (const float*)d_in[1];
    const float* centers = (const float*)d_in[2];
    const int*   pos     = (const int*)d_in[3];
    const int*   ci      = (const int*)d_in[4];
    const int*   vid     = (const int*)d_in[5];
    float* out = (float*)d_out;

    cudaFuncSetAttribute(sim_gemm_kernel,
                         cudaFuncAttributeMaxDynamicSharedMemorySize, DSMEM_BYTES);

    prep_kernel<<<PP * BB, 128>>>(feature, text);
    mask_scatter_kernel<<<(BB * KK + BB + 255) / 256, 256>>>(ci, pos);
    sim_gemm_kernel<<<dim3(8, PP), 256, DSMEM_BYTES>>>();
    neg_bf16_kernel<<<dim3(NTILES, PP), 256>>>(feature, centers);   // 4th: profiled
    sim_combine_kernel<<<2 * PP, 256>>>();
    valid_kernel<<<PP * BB, 128>>>();
    align_kernel<<<PP * BB, 128>>>();
    reduce_pos_kernel<<<PP * BB, 128>>>(feature, centers, ci);
    final_kernel<<<1, 128>>>(vid, ci, out);
}

// round 15
// speedup vs baseline: 4.3225x; 1.2153x over previous
#include <cuda_runtime.h>
#include <cuda_bf16.h>
#include <math.h>
#include <stdint.h>

#define PP 4
#define BB 128
#define DD 512
#define NN 32768
#define KK 10
#define NT 128
#define NTILES (NN/NT)   /* 256 */
#define SCALE_C 10.0f
#define INV_TEMP 2.0f
#define SIM_THR 0.7f
#define KLW 0.4916666666666667f
#define NEG_INF_F (-1e30f)

/* sim (tf32 legacy) geometry */
#define RS 20
#define STAGE_F (BB*RS)
#define NSTG 4
#define DSMEM_BYTES (2*NSTG*STAGE_F*4)   /* 81920 */

/* neg (bf16) geometry: 64B smem rows (one K=32 chunk), SW64 swizzle */
#define KCH 32
#define NCH (DD/KCH)            /* 16 chunks */
#define SRB 64                  /* smem row bytes */
#define ATILE (BB*SRB)          /* 8192 */
#define BTILE (BB*SRB)

// ---------------- device scratch ----------------
__device__ float g_img[PP*BB*DD];
__device__ float g_txt[PP*BB*DD];
__device__ __nv_bfloat16 g_featbf[PP*BB*DD];
__device__ float g_fn2[PP*BB];
__device__ float g_simpart[2*PP*4*BB*BB];
__device__ float g_imgsim[PP*BB*BB];
__device__ float g_txtsim[PP*BB*BB];
__device__ unsigned char g_negmask[NN];
__device__ float g_partial[PP*NTILES*BB];
__device__ float g_negsum[PP*BB];
__device__ float g_possum[PP*BB];
__device__ float g_valid[PP*BB];
__device__ float g_rowkl[PP*BB];

// ---------------- helpers ----------------
__device__ __forceinline__ float blockReduceSum(float v) {
    __shared__ float sh[32];
    int lane = threadIdx.x & 31, w = threadIdx.x >> 5;
    #pragma unroll
    for (int o = 16; o; o >>= 1) v += __shfl_down_sync(0xffffffffu, v, o);
    if (!lane) sh[w] = v;
    __syncthreads();
    int nw = (blockDim.x + 31) >> 5;
    v = (threadIdx.x < nw) ? sh[threadIdx.x] : 0.f;
    if (!w) {
        #pragma unroll
        for (int o = 16; o; o >>= 1) v += __shfl_down_sync(0xffffffffu, v, o);
    }
    __syncthreads();
    return v;  // valid on thread 0
}

__device__ __forceinline__ float blockReduceMax(float v) {
    __shared__ float shm[32];
    int lane = threadIdx.x & 31, w = threadIdx.x >> 5;
    #pragma unroll
    for (int o = 16; o; o >>= 1) v = fmaxf(v, __shfl_down_sync(0xffffffffu, v, o));
    if (!lane) shm[w] = v;
    __syncthreads();
    int nw = (blockDim.x + 31) >> 5;
    v = (threadIdx.x < nw) ? shm[threadIdx.x] : NEG_INF_F;
    if (!w) {
        #pragma unroll
        for (int o = 16; o; o >>= 1) v = fmaxf(v, __shfl_down_sync(0xffffffffu, v, o));
    }
    __syncthreads();
    return v;
}

__device__ __forceinline__ float bcastSum(float v) {
    float r = blockReduceSum(v);
    __shared__ float s;
    if (threadIdx.x == 0) s = r;
    __syncthreads();
    return s;
}

__device__ __forceinline__ float bcastMax(float v) {
    float r = blockReduceMax(v);
    __shared__ float s;
    if (threadIdx.x == 0) s = r;
    __syncthreads();
    return s;
}

__device__ __forceinline__ float tf32r(float x) {
    asm("cvt.rna.tf32.f32 %0, %0;" : "+f"(x));
    return x;
}

__device__ __forceinline__ uint32_t smem_u32(const void* p) {
    uint32_t a;
    asm("{ .reg .u64 t; cvta.to.shared.u64 t, %1; cvt.u32.u64 %0, t; }"
        : "=r"(a) : "l"(p));
    return a;
}

__device__ __forceinline__ void cp16(uint32_t dst, const void* src) {
    asm volatile("cp.async.cg.shared.global [%0], [%1], 16;\n" :: "r"(dst), "l"(src));
}

__device__ __forceinline__ void ldsm4(uint32_t* r, uint32_t addr) {
    asm volatile("ldmatrix.sync.aligned.m8n8.x4.shared.b16 {%0,%1,%2,%3}, [%4];\n"
                 : "=r"(r[0]), "=r"(r[1]), "=r"(r[2]), "=r"(r[3]) : "r"(addr));
}

__device__ __forceinline__ void mma_tf32(float* c, const uint32_t* a, const uint32_t* b) {
    asm volatile(
        "mma.sync.aligned.m16n8k8.row.col.f32.tf32.tf32.f32 "
        "{%0,%1,%2,%3}, {%4,%5,%6,%7}, {%8,%9}, {%0,%1,%2,%3};\n"
        : "+f"(c[0]), "+f"(c[1]), "+f"(c[2]), "+f"(c[3])
        : "r"(a[0]), "r"(a[1]), "r"(a[2]), "r"(a[3]), "r"(b[0]), "r"(b[1]));
}

__device__ __forceinline__ void mma_bf16(float* c, const uint32_t* a, const uint32_t* b) {
    asm volatile(
        "mma.sync.aligned.m16n8k16.row.col.f32.bf16.bf16.f32 "
        "{%0,%1,%2,%3}, {%4,%5,%6,%7}, {%8,%9}, {%0,%1,%2,%3};\n"
        : "+f"(c[0]), "+f"(c[1]), "+f"(c[2]), "+f"(c[3])
        : "r"(a[0]), "r"(a[1]), "r"(a[2]), "r"(a[3]), "r"(b[0]), "r"(b[1]));
}

__device__ __forceinline__ uint32_t bf2(float hi, float lo) {
    uint32_t r;
    asm("cvt.rn.bf16x2.f32 %0, %1, %2;" : "=r"(r) : "f"(hi), "f"(lo));
    return r;
}

__device__ __forceinline__ void sts128(uint32_t addr, uint32_t w0, uint32_t w1,
                                       uint32_t w2, uint32_t w3) {
    asm volatile("st.shared.v4.b32 [%0], {%1,%2,%3,%4};"
                 :: "r"(addr), "r"(w0), "r"(w1), "r"(w2), "r"(w3));
}

// ---------------- 1. normalize rows + fn2 + negmask + featbf ----------------
__global__ void prep_kernel(const float* __restrict__ feat,
                            const float* __restrict__ text) {
    int mi = blockIdx.x * 128 + threadIdx.x;
    if (mi < NN) g_negmask[mi] = 1;

    int pb = blockIdx.x;
    int p = pb / BB, b = pb % BB;
    const float* f = feat + (size_t)pb * DD;
    const float* t = text + ((size_t)b * PP + p) * DD;
    float s1 = 0.f, s2 = 0.f;
    for (int d = threadIdx.x; d < DD; d += 128) {
        float v = f[d]; s1 += v * v;
        float w = t[d]; s2 += w * w;
        g_featbf[(size_t)pb * DD + d] = __float2bfloat16(v);
    }
    __shared__ float inv1, inv2;
    float r1 = blockReduceSum(s1);
    if (threadIdx.x == 0) {
        g_fn2[pb] = r1;
        inv1 = 1.f / fmaxf(sqrtf(r1), 1e-12f);
    }
    float r2 = blockReduceSum(s2);
    if (threadIdx.x == 0) inv2 = 1.f / fmaxf(sqrtf(r2), 1e-12f);
    __syncthreads();
    for (int d = threadIdx.x; d < DD; d += 128) {
        g_img[(size_t)pb * DD + d] = tf32r(f[d] * inv1);
        g_txt[(size_t)pb * DD + d] = tf32r(t[d] * inv2);
    }
}

// ---------------- 2. neg mask scatter ----------------
__global__ void mask_scatter_kernel(const int* __restrict__ ci,
                                    const int* __restrict__ pos) {
    int i = blockIdx.x * 256 + threadIdx.x;
    if (i < BB * KK)            g_negmask[ci[i]] = 0;
    else if (i < BB * KK + BB)  g_negmask[pos[i - BB * KK]] = 0;
}

// ---------------- 3. NEG GEMM: bf16 mma, cp.async A (prebf16) + SW64 ---------
// grid (NTILES, P), 256 threads. A: 3-stage cp.async ring from g_featbf.
// B: LDG f32 -> cvt bf16 -> STS (conflict-free SW64), exact csq from regs.
__global__ __launch_bounds__(256, 2) void neg_bf16_kernel(
        const float* __restrict__ centers) {
    __shared__ __align__(16) char Asm[3 * ATILE];
    __shared__ __align__(16) char Bsm[2 * BTILE];
    __shared__ float redp[4][BB];
    __shared__ float cn2s[BB];

    int p = blockIdx.y, n0 = blockIdx.x * NT;
    const __nv_bfloat16* Af = g_featbf + (size_t)p * BB * DD;
    const float* Bp = centers + ((size_t)p * NN + n0) * DD;

    int t = threadIdx.x, lane = t & 31, wid = t >> 5;
    int g = lane >> 2, tig = lane & 3;
    int warpM = (wid >> 2) * 64;
    int warpN = (wid & 3) * 32;
    int q = lane >> 3, r = lane & 7;

    uint32_t sA = smem_u32(Asm), sB = smem_u32(Bsm);

    // staging mapping: row = t>>1, half = t&1 (units 2h, 2h+1 of the 4x16B row)
    int srow = t >> 1, half = t & 1;
    uint32_t swrow = (uint32_t)((srow & 6) << 3);
    uint32_t dA0 = sA + srow * SRB + (((2 * half) * 16) ^ swrow);
    uint32_t dA1 = sA + srow * SRB + (((2 * half + 1) * 16) ^ swrow);
    uint32_t dB0 = sB + srow * SRB + (((2 * half) * 16) ^ swrow);
    uint32_t dB1 = sB + srow * SRB + (((2 * half + 1) * 16) ^ swrow);
    const char* gAs = (const char*)Af + ((size_t)srow * DD + half * 16) * 2;
    const float4* gB = (const float4*)(Bp + (size_t)srow * DD + half * 16);

    // ldmatrix lane bases
    int rowa = warpM + (q & 1) * 8 + r;
    uint32_t aswz = (uint32_t)((rowa & 6) << 3);
    uint32_t aBase = sA + rowa * SRB;
    int rowb = warpN + (q >> 1) * 8 + r;
    uint32_t bswz = (uint32_t)((rowb & 6) << 3);
    uint32_t bBase = sB + rowb * SRB;

    float acc[4][4][4];
    #pragma unroll
    for (int i = 0; i < 4; i++)
        #pragma unroll
        for (int j = 0; j < 4; j++)
            #pragma unroll
            for (int z = 0; z < 4; z++) acc[i][j][z] = 0.f;

    // prologue: cp.async A chunks 0,1 (one commit each); LDG B chunk 0
    #pragma unroll
    for (int c0 = 0; c0 < 2; c0++) {
        const char* s = gAs + c0 * 64;   // chunk stride = 32 bf16 = 64B
        cp16(dA0 + c0 * ATILE, s);
        cp16(dA1 + c0 * ATILE, s + 16);
        asm volatile("cp.async.commit_group;\n");
    }
    float4 rb[4];
    #pragma unroll
    for (int i = 0; i < 4; i++) rb[i] = gB[i];

    float csq = 0.f;
    for (int c = 0; c < NCH; c++) {
        int bbuf = c & 1;
        uint32_t bo = (uint32_t)(bbuf * BTILE);
        // STS B(c) (bf16, SW64, conflict-free)
        sts128(dB0 + bo, bf2(rb[0].y, rb[0].x), bf2(rb[0].w, rb[0].z),
                         bf2(rb[1].y, rb[1].x), bf2(rb[1].w, rb[1].z));
        sts128(dB1 + bo, bf2(rb[2].y, rb[2].x), bf2(rb[2].w, rb[2].z),
                         bf2(rb[3].y, rb[3].x), bf2(rb[3].w, rb[3].z));
        #pragma unroll
        for (int i = 0; i < 4; i++)
            csq += rb[i].x*rb[i].x + rb[i].y*rb[i].y + rb[i].z*rb[i].z + rb[i].w*rb[i].w;

        // A(c) arrived (pending <= A(c+1)); then barrier makes everything visible
        asm volatile("cp.async.wait_group 1;\n");
        __syncthreads();

        // prefetch A(c+2) into ring slot (post-sync: slot's readers are done)
        if (c + 2 < NCH) {
            uint32_t ao2 = (uint32_t)(((c + 2) % 3) * ATILE);
            const char* s = gAs + (c + 2) * 64;
            cp16(dA0 + ao2, s);
            cp16(dA1 + ao2, s + 16);
        }
        asm volatile("cp.async.commit_group;\n");   // always (may be empty)

        // prefetch B(c+1) f32 into regs (overlaps mma)
        if (c + 1 < NCH) {
            #pragma unroll
            for (int i = 0; i < 4; i++) rb[i] = gB[(c + 1) * 8 + i];
        }

        uint32_t ao = (uint32_t)((c % 3) * ATILE);
        #pragma unroll
        for (int ks = 0; ks < 2; ks++) {
            uint32_t af_[4][4], bf_[4][2];
            uint32_t aoff = ao + ((((q >> 1) * 16) + ks * 32) ^ aswz);
            #pragma unroll
            for (int mt = 0; mt < 4; mt++)
                ldsm4(af_[mt], aBase + aoff + mt * (16 * SRB));
            uint32_t boff = bo + ((((q & 1) * 16) + ks * 32) ^ bswz);
            uint32_t tmp[4];
            ldsm4(tmp, bBase + boff);
            bf_[0][0]=tmp[0]; bf_[0][1]=tmp[1]; bf_[1][0]=tmp[2]; bf_[1][1]=tmp[3];
            ldsm4(tmp, bBase + boff + 16 * SRB);
            bf_[2][0]=tmp[0]; bf_[2][1]=tmp[1]; bf_[3][0]=tmp[2]; bf_[3][1]=tmp[3];
            #pragma unroll
            for (int mt = 0; mt < 4; mt++)
                #pragma unroll
                for (int nt = 0; nt < 4; nt++)
                    mma_bf16(acc[mt][nt], af_[mt], bf_[nt]);
        }
    }
    __syncthreads();

    // finalize cn2 (threads t, t^1 share row srow)
    csq += __shfl_xor_sync(0xffffffffu, csq, 1);
    if (half == 0) cn2s[srow] = csq;
    __syncthreads();

    float rsum[4][2];
    #pragma unroll
    for (int mt = 0; mt < 4; mt++) { rsum[mt][0] = 0.f; rsum[mt][1] = 0.f; }

    float f0[4], f1[4];
    #pragma unroll
    for (int mt = 0; mt < 4; mt++) {
        f0[mt] = g_fn2[p * BB + warpM + mt * 16 + g];
        f1[mt] = g_fn2[p * BB + warpM + mt * 16 + g + 8];
    }
    #pragma unroll
    for (int nt = 0; nt < 4; nt++) {
        int c0 = warpN + nt * 8 + 2 * tig;
        int c1 = c0 + 1;
        bool m0 = g_negmask[n0 + c0] != 0;
        bool m1 = g_negmask[n0 + c1] != 0;
        float cn0 = cn2s[c0], cn1 = cn2s[c1];
        #pragma unroll
        for (int mt = 0; mt < 4; mt++) {
            if (m0) {
                float pd2 = f0[mt] + cn0 - 2.f * acc[mt][nt][0];
                rsum[mt][0] += __expf(-SCALE_C * sqrtf(fmaxf(pd2, 1e-12f)));
                pd2 = f1[mt] + cn0 - 2.f * acc[mt][nt][2];
                rsum[mt][1] += __expf(-SCALE_C * sqrtf(fmaxf(pd2, 1e-12f)));
            }
            if (m1) {
                float pd2 = f0[mt] + cn1 - 2.f * acc[mt][nt][1];
                rsum[mt][0] += __expf(-SCALE_C * sqrtf(fmaxf(pd2, 1e-12f)));
                pd2 = f1[mt] + cn1 - 2.f * acc[mt][nt][3];
                rsum[mt][1] += __expf(-SCALE_C * sqrtf(fmaxf(pd2, 1e-12f)));
            }
        }
    }
    #pragma unroll
    for (int mt = 0; mt < 4; mt++) {
        #pragma unroll
        for (int h = 0; h < 2; h++) {
            float v = rsum[mt][h];
            v += __shfl_xor_sync(0xffffffffu, v, 1);
            v += __shfl_xor_sync(0xffffffffu, v, 2);
            rsum[mt][h] = v;
        }
    }
    if (tig == 0) {
        #pragma unroll
        for (int mt = 0; mt < 4; mt++) {
            redp[wid & 3][warpM + mt * 16 + g]     = rsum[mt][0];
            redp[wid & 3][warpM + mt * 16 + g + 8] = rsum[mt][1];
        }
    }
    __syncthreads();
    if (t < BB) {
        float s = redp[0][t] + redp[1][t] + redp[2][t] + redp[3][t];
        g_partial[((size_t)p * NTILES + blockIdx.x) * BB + t] = s;
    }
}

// ---------------- 3s. sim GEMM (tf32 legacy path, K-split x4) ----------------
__global__ __launch_bounds__(256) void sim_gemm_kernel() {
    extern __shared__ __align__(16) float dyn[];
    float* AsBase = dyn;
    float* BsBase = dyn + NSTG * STAGE_F;

    int p = blockIdx.y;
    const int NC = 8;
    int sel = blockIdx.x >> 2, kz = blockIdx.x & 3;
    const float* src = (sel ? g_txt : g_img) + (size_t)p * BB * DD + kz * 128;
    const float* Aptr = src;
    const float* Bptr = src;
    float* partdst = g_simpart + (size_t)((sel * PP + p) * 4 + kz) * BB * BB;

    int t = threadIdx.x;
    int lane = t & 31, wid = t >> 5;
    int g = lane >> 2, tig = lane & 3;
    int warpM = (wid >> 2) * 64;
    int warpN = (wid & 3) * 32;
    int q = lane >> 3, r = lane & 7;

    uint32_t sA = smem_u32(AsBase), sB = smem_u32(BsBase);
    uint32_t aRM = sA + (((warpM + (q & 1) * 8 + r) * RS + (q >> 1) * 4) << 2);
    uint32_t bRM = sB + (((warpN + (q >> 1) * 8 + r) * RS + (q & 1) * 4) << 2);

    int srow = t >> 1, kh = t & 1;
    uint32_t dA = sA + ((srow * RS + kh * 8) << 2);
    uint32_t dB = sB + ((srow * RS + kh * 8) << 2);
    const float* gA = Aptr + (size_t)srow * DD + kh * 8;
    const float* gB = Bptr + (size_t)srow * DD + kh * 8;

    float acc[4][4][4];
    #pragma unroll
    for (int i = 0; i < 4; i++)
        #pragma unroll
        for (int j = 0; j < 4; j++)
            #pragma unroll
            for (int z = 0; z < 4; z++) acc[i][j][z] = 0.f;

    #pragma unroll
    for (int s = 0; s < NSTG - 1; s++) {
        uint32_t off = (uint32_t)(s * STAGE_F) << 2;
        const float* gA2 = gA + s * 16;
        const float* gB2 = gB + s * 16;
        cp16(dA + off, gA2); cp16(dA + off + 16, gA2 + 4);
        cp16(dB + off, gB2); cp16(dB + off + 16, gB2 + 4);
        asm volatile("cp.async.commit_group;\n");
    }

    for (int c = 0; c < NC; c++) {
        asm volatile("cp.async.wait_group 2;\n");
        __syncthreads();

        if (c + NSTG - 1 < NC) {
            int s = c + NSTG - 1;
            uint32_t off = (uint32_t)((s & (NSTG - 1)) * STAGE_F) << 2;
            const float* gA2 = gA + s * 16;
            const float* gB2 = gB + s * 16;
            cp16(dA + off, gA2); cp16(dA + off + 16, gA2 + 4);
            cp16(dB + off, gB2); cp16(dB + off + 16, gB2 + 4);
        }
        asm volatile("cp.async.commit_group;\n");

        int buf = c & (NSTG - 1);
        uint32_t soff = (uint32_t)(buf * STAGE_F) << 2;
        #pragma unroll
        for (int ks = 0; ks < 2; ks++) {
            uint32_t koff = soff + ks * 32;
            uint32_t af[4][4], bf[4][2];
            #pragma unroll
            for (int mt = 0; mt < 4; mt++)
                ldsm4(af[mt], aRM + koff + mt * (16 * RS * 4));
            {
                uint32_t tmp[4];
                ldsm4(tmp, bRM + koff);
                bf[0][0]=tmp[0]; bf[0][1]=tmp[1]; bf[1][0]=tmp[2]; bf[1][1]=tmp[3];
                ldsm4(tmp, bRM + koff + 16 * RS * 4);
                bf[2][0]=tmp[0]; bf[2][1]=tmp[1]; bf[3][0]=tmp[2]; bf[3][1]=tmp[3];
            }
            #pragma unroll
            for (int mt = 0; mt < 4; mt++)
                #pragma unroll
                for (int nt = 0; nt < 4; nt++)
                    mma_tf32(acc[mt][nt], af[mt], bf[nt]);
        }
    }
    __syncthreads();

    #pragma unroll
    for (int mt = 0; mt < 4; mt++) {
        int r0 = warpM + mt * 16 + g;
        int r1 = r0 + 8;
        #pragma unroll
        for (int nt = 0; nt < 4; nt++) {
            int c0 = warpN + nt * 8 + 2 * tig;
            partdst[r0 * BB + c0]     = acc[mt][nt][0];
            partdst[r0 * BB + c0 + 1] = acc[mt][nt][1];
            partdst[r1 * BB + c0]     = acc[mt][nt][2];
            partdst[r1 * BB + c0 + 1] = acc[mt][nt][3];
        }
    }
}

// ---------------- 3b. combine sim K-split partials ----------------
__global__ void sim_combine_kernel() {
    int sp = blockIdx.x;
    int sel = sp >> 2, p = sp & 3;
    const float4* b0 = (const float4*)(g_simpart + (size_t)sp * 4 * BB * BB);
    const float4* b1 = b0 + (BB * BB / 4);
    const float4* b2 = b1 + (BB * BB / 4);
    const float4* b3 = b2 + (BB * BB / 4);
    float4* dst = (float4*)((sel ? g_txtsim : g_imgsim) + (size_t)p * BB * BB);
    for (int i = threadIdx.x; i < BB * BB / 4; i += 256) {
        float4 a = b0[i], b = b1[i], c = b2[i], d = b3[i];
        float4 o;
        o.x = (a.x + b.x + c.x + d.x) * INV_TEMP;
        o.y = (a.y + b.y + c.y + d.y) * INV_TEMP;
        o.z = (a.z + b.z + c.z + d.z) * INV_TEMP;
        o.w = (a.w + b.w + c.w + d.w) * INV_TEMP;
        dst[i] = o;
    }
}

// ---------------- 4a. per-row validity ----------------
__global__ void valid_kernel() {
    int pb = blockIdx.x;
    int c = threadIdx.x;
    float im = g_imgsim[(size_t)pb * BB + c];
    float tx = g_txtsim[(size_t)pb * BB + c];
    int any = __syncthreads_or((im > SIM_THR && tx > SIM_THR) ? 1 : 0);
    if (c == 0) g_valid[pb] = any ? 1.f : 0.f;
}

// ---------------- 4b. align / KL per row ----------------
__global__ void align_kernel() {
    int pb = blockIdx.x;
    int p = pb / BB;
    int c = threadIdx.x;
    float im = g_imgsim[(size_t)pb * BB + c];
    float tx = g_txtsim[(size_t)pb * BB + c];
    bool vc = g_valid[p * BB + c] > 0.5f;

    float mi = bcastMax(vc ? im : NEG_INF_F);
    float mt = bcastMax(vc ? tx : NEG_INF_F);
    float si = bcastSum(vc ? expf(im - mi) : 0.f);
    float st = bcastSum(vc ? expf(tx - mt) : 0.f);
    float lsei = logf(si) + mi;
    float lset = logf(st) + mt;

    float kl = 0.f;
    if (vc) {
        float ilp = im - lsei;
        float tlp = tx - lset;
        kl = expf(tlp) * (tlp - ilp) + expf(ilp) * (ilp - tlp);
    }
    float ks = blockReduceSum(kl);
    if (c == 0) {
        bool vb = g_valid[pb] > 0.5f;
        g_rowkl[pb] = vb ? 0.5f * ks : 0.f;
    }
}

// ---------------- 5. fused neg-reduce + positive distances ----------------
__global__ void reduce_pos_kernel(const float* __restrict__ feat,
                                  const float* __restrict__ centers,
                                  const int* __restrict__ ci) {
    int pb = blockIdx.x;
    int p = pb / BB, b = pb % BB;
    int t = threadIdx.x, lane = t & 31, wid = t >> 5;

    float s = g_partial[((size_t)p * NTILES + t) * BB + b]
            + g_partial[((size_t)p * NTILES + t + 128) * BB + b];
    float rneg = blockReduceSum(s);
    if (t == 0) g_negsum[pb] = rneg;

    __shared__ float wsum[4];
    const float4* f = (const float4*)(feat + (size_t)pb * DD);
    float fn2v = g_fn2[pb];
    float part = 0.f;
    for (int k = wid; k < KK; k += 4) {
        int idx = ci[b * KK + k];
        const float4* c = (const float4*)(centers + ((size_t)p * NN + idx) * DD);
        float dot = 0.f, pn2 = 0.f;
        #pragma unroll
        for (int qq = lane; qq < DD / 4; qq += 32) {
            float4 a = f[qq], bv = c[qq];
            dot += a.x * bv.x + a.y * bv.y + a.z * bv.z + a.w * bv.w;
            pn2 += bv.x * bv.x + bv.y * bv.y + bv.z * bv.z + bv.w * bv.w;
        }
        #pragma unroll
        for (int o = 16; o; o >>= 1) {
            dot += __shfl_down_sync(0xffffffffu, dot, o);
            pn2 += __shfl_down_sync(0xffffffffu, pn2, o);
        }
        if (lane == 0) {
            float pd2 = fn2v + pn2 - 2.f * dot;
            part += expf(-SCALE_C * sqrtf(fmaxf(pd2, 1e-12f)));
        }
    }
    if (lane == 0) wsum[wid] = part;
    __syncthreads();
    if (t == 0) g_possum[pb] = wsum[0] + wsum[1] + wsum[2] + wsum[3];
}

// ---------------- 6. final combine + pos_vid gather ----------------
__global__ void final_kernel(const int* __restrict__ vid,
                             const int* __restrict__ ci,
                             float* __restrict__ out) {
    int b = threadIdx.x;
    for (int i = b; i < BB * KK; i += 128) out[3 + i] = (float)vid[ci[i]];

    __shared__ float sacc, salign;
    if (b == 0) { sacc = 0.f; salign = 0.f; }
    __syncthreads();
    for (int p = 0; p < PP; p++) {
        float v = logf(g_negsum[p * BB + b]) - logf(g_possum[p * BB + b]);
        float r = blockReduceSum(v);
        if (b == 0) {
            float lp = r / (float)BB;
            if (isnan(lp)) lp = 0.f;
            sacc += lp;
        }
        float rk = blockReduceSum(g_rowkl[p * BB + b]);
        float nv = blockReduceSum(g_valid[p * BB + b]);
        if (b == 0) {
            int n = (int)(nv + 0.5f);
            salign += (n > 0) ? rk / (float)n : 0.f;
        }
        __syncthreads();
    }
    if (b == 0) {
        float contrastive = sacc / (float)PP;
        float align = salign;
        out[0] = contrastive + KLW * align;
        out[1] = contrastive;
        out[2] = align;
    }
}

// ---------------- launch ----------------
extern "C" void kernel_launch(void* const* d_in, const int* in_sizes, int n_in,
                              void* d_out, int out_size) {
    const float* feature = (const float*)d_in[0];
    const float* text    = (const float*)d_in[1];
    const float* centers = (const float*)d_in[2];
    const int*   pos     = (const int*)d_in[3];
    const int*   ci      = (const int*)d_in[4];
    const int*   vid     = (const int*)d_in[5];
    float* out = (float*)d_out;

    cudaFuncSetAttribute(sim_gemm_kernel,
                         cudaFuncAttributeMaxDynamicSharedMemorySize, DSMEM_BYTES);

    prep_kernel<<<PP * BB, 128>>>(feature, text);
    mask_scatter_kernel<<<(BB * KK + BB + 255) / 256, 256>>>(ci, pos);
    sim_gemm_kernel<<<dim3(8, PP), 256, DSMEM_BYTES>>>();
    neg_bf16_kernel<<<dim3(NTILES, PP), 256>>>(centers);   // 4th: profiled
    sim_combine_kernel<<<2 * PP, 256>>>();
    valid_kernel<<<PP * BB, 128>>>();
    align_kernel<<<PP * BB, 128>>>();
    reduce_pos_kernel<<<PP * BB, 128>>>(feature, centers, ci);
    final_kernel<<<1, 128>>>(vid, ci, out);
}